// round 9
// baseline (speedup 1.0000x reference)
#include <cuda_runtime.h>
#include <cuda_bf16.h>
#include <math.h>
#include <cstdint>

#define Bsz  1024
#define INd  1024
#define OUTd 1024
#define NQw  10
#define Gg   4
#define DPT  4
#define QD   1024
#define GQ   4096   // G * QDIM

typedef unsigned long long u64;

// ---------------- scratch (device globals: no allocation allowed) ----------
__device__ float g_xq[Bsz * GQ];            // 16 MB (GEMM-in output, fp32)
__device__ float g_ang[Bsz * Gg * NQw];     // 160 KB
__device__ __nv_bfloat16 g_ph[Bsz * GQ];    // probs hi
__device__ __nv_bfloat16 g_pl[Bsz * GQ];    // probs lo
__device__ __nv_bfloat16 g_xh[Bsz * INd];   // (x*scale) hi
__device__ __nv_bfloat16 g_xl[Bsz * INd];
__device__ __nv_bfloat16 g_wih[GQ * INd];   // proj_in_w hi/lo
__device__ __nv_bfloat16 g_wil[GQ * INd];
__device__ __nv_bfloat16 g_woh[OUTd * GQ];  // proj_out_w hi/lo
__device__ __nv_bfloat16 g_wol[OUTd * GQ];

// ================= small PTX helpers (family-stable only; NO tcgen05) ======
__device__ __forceinline__ uint32_t smem_u32(const void* p){
    uint32_t a;
    asm("{ .reg .u64 t; cvta.to.shared.u64 t, %1; cvt.u32.u64 %0, t; }" : "=r"(a) : "l"(p));
    return a;
}
__device__ __forceinline__ void cp16(uint32_t s, const void* g){
    asm volatile("cp.async.cg.shared.global [%0], [%1], 16;" :: "r"(s), "l"(g) : "memory");
}
__device__ __forceinline__ void ldm4(uint32_t* r, uint32_t addr){
    asm volatile("ldmatrix.sync.aligned.m8n8.x4.shared.b16 {%0,%1,%2,%3}, [%4];"
                 : "=r"(r[0]), "=r"(r[1]), "=r"(r[2]), "=r"(r[3]) : "r"(addr));
}
__device__ __forceinline__ void mma_bf16(float* c, const uint32_t* a, const uint32_t* b){
    asm volatile(
        "mma.sync.aligned.m16n8k16.row.col.f32.bf16.bf16.f32 "
        "{%0,%1,%2,%3}, {%4,%5,%6,%7}, {%8,%9}, {%0,%1,%2,%3};"
        : "+f"(c[0]), "+f"(c[1]), "+f"(c[2]), "+f"(c[3])
        : "r"(a[0]), "r"(a[1]), "r"(a[2]), "r"(a[3]), "r"(b[0]), "r"(b[1]));
}

// ---- packed f32x2 (PTX ISA 8.6, sm_100+ family-generic) ----
__device__ __forceinline__ u64 f2fma(u64 a, u64 b, u64 c){
    u64 d; asm("fma.rn.f32x2 %0, %1, %2, %3;" : "=l"(d) : "l"(a), "l"(b), "l"(c)); return d;
}
__device__ __forceinline__ u64 f2mul(u64 a, u64 b){
    u64 d; asm("mul.rn.f32x2 %0, %1, %2;" : "=l"(d) : "l"(a), "l"(b)); return d;
}
__device__ __forceinline__ u64 pk2(float lo, float hi){
    u64 r;
    asm("mov.b64 %0, {%1, %2};" : "=l"(r) : "r"(__float_as_uint(lo)), "r"(__float_as_uint(hi)));
    return r;
}
__device__ __forceinline__ u64 dup2(float x){ return pk2(x, x); }
__device__ __forceinline__ void unpk(u64 v, float& a, float& b){
    uint32_t x, y;
    asm("mov.b64 {%0, %1}, %2;" : "=r"(x), "=r"(y) : "l"(v));
    a = __uint_as_float(x); b = __uint_as_float(y);
}
__device__ __forceinline__ u64 swp(u64 v){ float a, b; unpk(v, a, b); return pk2(b, a); }

// ================= bf16 split (hi + lo), float4-vectorized =================
__global__ void __launch_bounds__(256)
split_bf16v(const float4* __restrict__ src, const float* __restrict__ scale,
            __nv_bfloat162* __restrict__ hi, __nv_bfloat162* __restrict__ lo, int n4)
{
    int i = blockIdx.x * 256 + threadIdx.x;
    if (i < n4){
        float4 v = src[i];
        if (scale){
            int k = (4 * i) & (INd - 1);
            v.x *= scale[k]; v.y *= scale[k + 1]; v.z *= scale[k + 2]; v.w *= scale[k + 3];
        }
        __nv_bfloat16 hx = __float2bfloat16(v.x), hy = __float2bfloat16(v.y);
        __nv_bfloat16 hz = __float2bfloat16(v.z), hw = __float2bfloat16(v.w);
        hi[2 * i]     = __nv_bfloat162(hx, hy);
        hi[2 * i + 1] = __nv_bfloat162(hz, hw);
        lo[2 * i]     = __nv_bfloat162(__float2bfloat16(v.x - __bfloat162float(hx)),
                                       __float2bfloat16(v.y - __bfloat162float(hy)));
        lo[2 * i + 1] = __nv_bfloat162(__float2bfloat16(v.z - __bfloat162float(hz)),
                                       __float2bfloat16(v.w - __bfloat162float(hw)));
    }
}

// ================= HMMA GEMM: C[M,N] = Ahl[M,K] @ Bhl[N,K]^T + bias ========
// bf16x3 split: Ahi*Bhi + Ahi*Blo + Alo*Bhi, fp32 accum.
// CTA tile 128 x BN, BK=64, 8 warps (4m x 2n), warp tile 32 x (BN/2).
// 2-stage double buffer; prefetch after compute (R4-validated ordering).
// SMEM rows: 64 bf16 data + 8 pad = 144B -> conflict-free ldmatrix + stores.
template<int BN>
__global__ void __launch_bounds__(256)
mma_gemm(int M, int N, int K,
         const __nv_bfloat16* __restrict__ Ahi, const __nv_bfloat16* __restrict__ Alo,
         const __nv_bfloat16* __restrict__ Bhi, const __nv_bfloat16* __restrict__ Blo,
         const float* __restrict__ bias, float* __restrict__ C)
{
    constexpr int A_BY = 128 * 144;       // 128 rows x 144B
    constexpr int B_BY = BN * 144;
    constexpr int STG_ = 2 * A_BY + 2 * B_BY;
    constexpr int NT   = BN / 16;         // n8 tiles per warp
    extern __shared__ char smc[];

    const int tid  = threadIdx.x;
    const int wid  = tid >> 5, lane = tid & 31;
    const int grp  = lane >> 2, tig = lane & 3;
    const int wm   = wid & 3,  wn = wid >> 2;       // 4 x 2 warp grid
    const int m0   = blockIdx.y * 128, n0 = blockIdx.x * BN;
    const uint32_t sb = smem_u32(smc);

    // ldmatrix lane-address components
    const int a_row = lane & 15, a_off = (lane >> 4) << 4;          // A .x4
    const int b_row = ((lane >> 4) << 3) + (lane & 7);              // B .x4 (2 tiles)
    const int b_off = ((lane >> 3) & 1) << 4;

    float c[2][NT][4];
#pragma unroll
    for (int mt = 0; mt < 2; mt++)
#pragma unroll
        for (int nt = 0; nt < NT; nt++)
#pragma unroll
            for (int q = 0; q < 4; q++) c[mt][nt][q] = 0.f;

    const int nk = K >> 6;                // K chunks of 64

    auto do_prefetch = [&](int i){
        const int st = i & 1;
        const int k0 = i << 6;
        const uint32_t ba = sb + st * STG_;
#pragma unroll
        for (int v = tid; v < 1024; v += 256){
            int r = v >> 3, ch = v & 7;
            uint32_t so = ba + r * 144 + ch * 16;
            cp16(so,        Ahi + (size_t)(m0 + r) * K + k0 + ch * 8);
            cp16(so + A_BY, Alo + (size_t)(m0 + r) * K + k0 + ch * 8);
        }
#pragma unroll
        for (int v = tid; v < BN * 8; v += 256){
            int r = v >> 3, ch = v & 7;
            uint32_t so = ba + 2 * A_BY + r * 144 + ch * 16;
            cp16(so,        Bhi + (size_t)(n0 + r) * K + k0 + ch * 8);
            cp16(so + B_BY, Blo + (size_t)(n0 + r) * K + k0 + ch * 8);
        }
        asm volatile("cp.async.commit_group;" ::: "memory");
    };

    do_prefetch(0);
    do_prefetch(1);

    for (int i = 0; i < nk; i++){
        if (i + 2 <= nk) asm volatile("cp.async.wait_group 1;" ::: "memory");
        else             asm volatile("cp.async.wait_group 0;" ::: "memory");
        __syncthreads();

        const uint32_t ba = sb + (i & 1) * STG_;
        const uint32_t bb = ba + 2 * A_BY;

#pragma unroll
        for (int kk = 0; kk < 4; kk++){
            uint32_t ah[2][4], al[2][4];
#pragma unroll
            for (int mt = 0; mt < 2; mt++){
                const uint32_t oa = ba + (wm * 32 + mt * 16 + a_row) * 144 + kk * 32 + a_off;
                ldm4(ah[mt], oa);
                ldm4(al[mt], oa + A_BY);
            }
            uint32_t bh[NT][2], bl[NT][2];
#pragma unroll
            for (int np = 0; np < NT / 2; np++){
                const uint32_t ob = bb + (wn * (NT * 8) + np * 16 + b_row) * 144 + kk * 32 + b_off;
                uint32_t t4[4];
                ldm4(t4, ob);
                bh[2*np][0] = t4[0]; bh[2*np][1] = t4[1];
                bh[2*np+1][0] = t4[2]; bh[2*np+1][1] = t4[3];
                ldm4(t4, ob + B_BY);
                bl[2*np][0] = t4[0]; bl[2*np][1] = t4[1];
                bl[2*np+1][0] = t4[2]; bl[2*np+1][1] = t4[3];
            }
#pragma unroll
            for (int mt = 0; mt < 2; mt++)
#pragma unroll
                for (int nt = 0; nt < NT; nt++){
                    mma_bf16(c[mt][nt], ah[mt], bh[nt]);
                    mma_bf16(c[mt][nt], ah[mt], bl[nt]);
                    mma_bf16(c[mt][nt], al[mt], bh[nt]);
                }
        }
        __syncthreads();
        if (i + 2 < nk) do_prefetch(i + 2);
    }

    // epilogue
#pragma unroll
    for (int mt = 0; mt < 2; mt++){
        const int row0 = m0 + wm * 32 + mt * 16 + grp;
#pragma unroll
        for (int nt = 0; nt < NT; nt++){
            const int col = n0 + wn * (NT * 8) + nt * 8 + 2 * tig;
            const float b0 = bias[col], b1 = bias[col + 1];
            float2 v0 = make_float2(c[mt][nt][0] + b0, c[mt][nt][1] + b1);
            float2 v1 = make_float2(c[mt][nt][2] + b0, c[mt][nt][3] + b1);
            *(float2*)&C[(size_t)row0       * N + col] = v0;
            *(float2*)&C[(size_t)(row0 + 8) * N + col] = v1;
        }
    }
}

// ---------------- angles: ang[b, j] = tanh((x*s) . reup_w[j] + reup_b[j]) * pi
__global__ void __launch_bounds__(320)
angles_kernel(const float* __restrict__ x, const float* __restrict__ inp_scale,
              const float* __restrict__ reup_w, const float* __restrict__ reup_b,
              float* __restrict__ ang)
{
    __shared__ float xs[INd];
    int b = blockIdx.x;
    for (int k = threadIdx.x; k < INd; k += blockDim.x)
        xs[k] = x[(size_t)b * INd + k] * inp_scale[k];
    __syncthreads();
    int warp = threadIdx.x >> 5, lane = threadIdx.x & 31;
#pragma unroll
    for (int q = 0; q < 4; q++){
        int j = warp * 4 + q;            // j in [0,40)
        const float* w = reup_w + (size_t)j * INd;
        float acc = 0.f;
        for (int k = lane; k < INd; k += 32) acc = fmaf(xs[k], w[k], acc);
#pragma unroll
        for (int o = 16; o; o >>= 1) acc += __shfl_xor_sync(0xffffffffu, acc, o);
        if (lane == 0)
            ang[(size_t)b * (Gg * NQw) + j] = tanhf(acc + reup_b[j]) * 3.14159265358979323846f;
    }
}

// ---------------- complex 2x2 helpers ----------------
struct C2 { float re, im; };
__device__ __forceinline__ C2 cmul(C2 a, C2 b){ return {a.re*b.re - a.im*b.im, a.re*b.im + a.im*b.re}; }
__device__ __forceinline__ C2 cadd(C2 a, C2 b){ return {a.re+b.re, a.im+b.im}; }
struct M2 { C2 m00, m01, m10, m11; };
__device__ __forceinline__ M2 mmul(M2 A, M2 B){  // A @ B
    M2 r;
    r.m00 = cadd(cmul(A.m00,B.m00), cmul(A.m01,B.m10));
    r.m01 = cadd(cmul(A.m00,B.m01), cmul(A.m01,B.m11));
    r.m10 = cadd(cmul(A.m10,B.m00), cmul(A.m11,B.m10));
    r.m11 = cadd(cmul(A.m10,B.m01), cmul(A.m11,B.m11));
    return r;
}
__device__ __forceinline__ M2 ry_m(float t){
    float c=cosf(0.5f*t), s=sinf(0.5f*t);
    return {{c,0.f},{-s,0.f},{s,0.f},{c,0.f}};
}
__device__ __forceinline__ M2 rx_m(float t){
    float c=cosf(0.5f*t), s=sinf(0.5f*t);
    return {{c,0.f},{0.f,-s},{0.f,-s},{c,0.f}};
}
__device__ __forceinline__ M2 u3_m(float t,float p,float l){
    float c=cosf(0.5f*t), s=sinf(0.5f*t);
    float cp=cosf(p), sp=sinf(p), cl=cosf(l), sl=sinf(l);
    M2 r;
    r.m00 = {c, 0.f};
    r.m01 = {-cl*s, -sl*s};
    r.m10 = {cp*s, sp*s};
    r.m11 = {(cp*cl - sp*sl)*c, (sp*cl + cp*sl)*c};
    return r;
}

// CNOT-ring permutation is XOR-linear: perm(a^b) = perm(a)^perm(b)
__device__ constexpr int permL(int y){
    for (int k = 9; k >= 0; --k){
        int cb  = 9 - k;
        int tb2 = 9 - ((k + 1) % 10);
        y ^= ((y >> cb) & 1) << tb2;
    }
    return y;
}

// ================= quantum circuit: one WARP per (b,g) state ===============
// Lane l holds amps l*32+j (j=0..31), packed 2 amps per u64 over amp bit 0.
// Wires 0-4: lane-bit butterflies (shfl_xor). Wires 5-8: in-register.
// Wire 9: within-u64. Perm via dual SMEM buffers (no reg temp array).
// __launch_bounds__(128, 4): cap 128 regs -> 16 warps/SM guaranteed.
__global__ void __launch_bounds__(128, 4)
quantum_pk(const float* __restrict__ xq, const float* __restrict__ ang,
           const float* __restrict__ qw, const float* __restrict__ us,
           const float* __restrict__ mw,
           __nv_bfloat16* __restrict__ ph, __nv_bfloat16* __restrict__ pl)
{
    __shared__ __align__(16) float ssR[4][34 * 32];
    __shared__ __align__(16) float ssI[4][34 * 32];
    const int wid = threadIdx.x >> 5, l = threadIdx.x & 31;
    const int s = blockIdx.x * 4 + wid;
    const int b = s >> 2, g = s & 3;
    const unsigned FULL = 0xffffffffu;
    float* bR = ssR[wid];
    float* bI = ssI[wid];

    // permutation basis: B* are compile-time constants; zl is per-lane
    constexpr int B1 = permL(1), B2 = permL(2), B4 = permL(4), B8 = permL(8), B16 = permL(16);
    const int zl = permL(l << 5);

    // ---- load (coalesced) -> transpose via smem -> packed registers ----
    const float* xrow = xq + (size_t)b * GQ + (size_t)g * QD;
#pragma unroll
    for (int j = 0; j < 32; j++) bR[j * 34 + l] = xrow[j * 32 + l];
    __syncwarp();
    u64 vr[16], vi[16];
    u64 acc2 = 0ull;
#pragma unroll
    for (int k = 0; k < 16; k++){
        vr[k] = *(const u64*)&bR[l * 34 + 2 * k];
        acc2  = f2fma(vr[k], vr[k], acc2);
        vi[k] = 0ull;
    }
    float na, nb; unpk(acc2, na, nb);
    float nrm = na + nb;
#pragma unroll
    for (int o = 16; o; o >>= 1) nrm += __shfl_xor_sync(FULL, nrm, o);
    const u64 iv = dup2(1.0f / (sqrtf(nrm) + 1e-9f));
#pragma unroll
    for (int k = 0; k < 16; k++) vr[k] = f2mul(iv, vr[k]);
    __syncwarp();

    for (int r = 0; r < 5; r++){
        // ---- lanes 0..9 build fused 2x2 gate matrix for wire l ----
        float m0=0,m1=0,m2=0,m3=0,m4=0,m5=0,m6=0,m7=0;
        if (l < NQw){
            const int i = l;
            M2 M;
            if (r < 4){
                float a = ang[(size_t)b * (Gg * NQw) + g * NQw + i];
                float theta = a * us[(g * DPT + r) * NQw + i];
                if (r > 0) theta += qw[((g * DPT + (r - 1)) * NQw + i) * 3 + 2];
                const float* q = qw + ((size_t)(g * DPT + r) * NQw + i) * 3;
                M = mmul(ry_m(q[1]), mmul(rx_m(q[0]), ry_m(theta)));
            } else {
                const float* m = mw + ((size_t)g * NQw + i) * 3;
                float t2 = qw[((g * DPT + 3) * NQw + i) * 3 + 2];
                M = mmul(u3_m(m[0], m[1], m[2]), ry_m(t2));
            }
            m0=M.m00.re; m1=M.m00.im; m2=M.m01.re; m3=M.m01.im;
            m4=M.m10.re; m5=M.m10.im; m6=M.m11.re; m7=M.m11.im;
        }

        // ---- wires 0..4: lane-bit butterflies ----
#pragma unroll
        for (int i = 0; i < 5; i++){
            const float c0=__shfl_sync(FULL,m0,i), c1=__shfl_sync(FULL,m1,i);
            const float c2=__shfl_sync(FULL,m2,i), c3=__shfl_sync(FULL,m3,i);
            const float c4=__shfl_sync(FULL,m4,i), c5=__shfl_sync(FULL,m5,i);
            const float c6=__shfl_sync(FULL,m6,i), c7=__shfl_sync(FULL,m7,i);
            const int lb = 4 - i, msk = 1 << lb;
            const bool hb = (l >> lb) & 1;
            const float aR = hb ? c6 : c0, aI = hb ? c7 : c1;   // m11 : m00
            const float bRc = hb ? c4 : c2, bIc = hb ? c5 : c3; // m10 : m01
            const u64 PaR = dup2(aR), NaI = dup2(-aI), QaI = dup2(aI);
            const u64 PbR = dup2(bRc), NbI = dup2(-bIc), QbI = dup2(bIc);
#pragma unroll
            for (int k = 0; k < 16; k++){
                u64 pr  = __shfl_xor_sync(FULL, vr[k], msk);
                u64 pim = __shfl_xor_sync(FULL, vi[k], msk);
                u64 orr = vr[k], oii = vi[k];
                vr[k] = f2fma(PaR, orr, f2fma(NaI, oii, f2fma(PbR, pr,  f2mul(NbI, pim))));
                vi[k] = f2fma(PaR, oii, f2fma(QaI, orr, f2fma(PbR, pim, f2mul(QbI, pr))));
            }
        }

        // ---- wires 5..8: in-register pair-index butterflies ----
#pragma unroll
        for (int w = 5; w <= 8; w++){
            const float c0=__shfl_sync(FULL,m0,w), c1=__shfl_sync(FULL,m1,w);
            const float c2=__shfl_sync(FULL,m2,w), c3=__shfl_sync(FULL,m3,w);
            const float c4=__shfl_sync(FULL,m4,w), c5=__shfl_sync(FULL,m5,w);
            const float c6=__shfl_sync(FULL,m6,w), c7=__shfl_sync(FULL,m7,w);
            const u64 Pr00=dup2(c0), Ni00=dup2(-c1), Qi00=dup2(c1);
            const u64 Pr01=dup2(c2), Ni01=dup2(-c3), Qi01=dup2(c3);
            const u64 Pr10=dup2(c4), Ni10=dup2(-c5), Qi10=dup2(c5);
            const u64 Pr11=dup2(c6), Ni11=dup2(-c7), Qi11=dup2(c7);
            const int SBc = 8 - w;               // pair-index bit
#pragma unroll
            for (int kk = 0; kk < 8; kk++){
                const int k0 = ((kk >> SBc) << (SBc + 1)) | (kk & ((1 << SBc) - 1));
                const int k1 = k0 | (1 << SBc);
                u64 a0r = vr[k0], a0i = vi[k0], a1r = vr[k1], a1i = vi[k1];
                vr[k0] = f2fma(Pr00, a0r, f2fma(Ni00, a0i, f2fma(Pr01, a1r, f2mul(Ni01, a1i))));
                vi[k0] = f2fma(Pr00, a0i, f2fma(Qi00, a0r, f2fma(Pr01, a1i, f2mul(Qi01, a1r))));
                vr[k1] = f2fma(Pr10, a0r, f2fma(Ni10, a0i, f2fma(Pr11, a1r, f2mul(Ni11, a1i))));
                vi[k1] = f2fma(Pr10, a0i, f2fma(Qi10, a0r, f2fma(Pr11, a1i, f2mul(Qi11, a1r))));
            }
        }

        // ---- wire 9: within-u64 butterfly ----
        {
            const float c0=__shfl_sync(FULL,m0,9), c1=__shfl_sync(FULL,m1,9);
            const float c2=__shfl_sync(FULL,m2,9), c3=__shfl_sync(FULL,m3,9);
            const float c4=__shfl_sync(FULL,m4,9), c5=__shfl_sync(FULL,m5,9);
            const float c6=__shfl_sync(FULL,m6,9), c7=__shfl_sync(FULL,m7,9);
            const u64 P1 = pk2(c0, c6),  P2 = pk2(c2, c4);
            const u64 N1 = pk2(-c1, -c7), N2 = pk2(-c3, -c5);
            const u64 Q1 = pk2(c1, c7),  Q2 = pk2(c3, c5);
#pragma unroll
            for (int k = 0; k < 16; k++){
                u64 xr = vr[k], xi_ = vi[k];
                u64 xsr = swp(xr), xsi = swp(xi_);
                vr[k] = f2fma(P1, xr,  f2fma(P2, xsr, f2fma(N1, xi_, f2mul(N2, xsi))));
                vi[k] = f2fma(P1, xi_, f2fma(P2, xsi, f2fma(Q1, xr,  f2mul(Q2, xsr))));
            }
        }

        // ---- CNOT-ring permutation (rounds 0..3): dual-buffer, one pass ----
        if (r < 4){
            __syncwarp();
#pragma unroll
            for (int k = 0; k < 16; k++){
                *(u64*)&bR[l * 34 + 2 * k] = vr[k];
                *(u64*)&bI[l * 34 + 2 * k] = vi[k];
            }
            __syncwarp();
#pragma unroll
            for (int k = 0; k < 16; k++){
                constexpr auto zj = [](int j){
                    return ((j&1)?B1:0) ^ ((j&2)?B2:0) ^ ((j&4)?B4:0) ^ ((j&8)?B8:0) ^ ((j&16)?B16:0);
                };
                const int z0 = zl ^ zj(2 * k);
                const int z1 = zl ^ zj(2 * k + 1);
                const int a0 = (z0 >> 5) * 34 + (z0 & 31);
                const int a1 = (z1 >> 5) * 34 + (z1 & 31);
                vr[k] = pk2(bR[a0], bR[a1]);
                vi[k] = pk2(bI[a0], bI[a1]);
            }
            __syncwarp();
        }
    }

    // ---- probabilities: packed square-sum, transpose, bf16 hi/lo store ----
    __syncwarp();
#pragma unroll
    for (int k = 0; k < 16; k++)
        *(u64*)&bR[l * 34 + 2 * k] = f2fma(vr[k], vr[k], f2mul(vi[k], vi[k]));
    __syncwarp();
    const size_t o = (size_t)b * GQ + (size_t)g * QD;
#pragma unroll
    for (int j = 0; j < 32; j++){
        float p = bR[j * 34 + l];
        __nv_bfloat16 h = __float2bfloat16(p);
        ph[o + j * 32 + l] = h;
        pl[o + j * 32 + l] = __float2bfloat16(p - __bfloat162float(h));
    }
}

// ---------------- launch ----------------
extern "C" void kernel_launch(void* const* d_in, const int* in_sizes, int n_in,
                              void* d_out, int out_size)
{
    const float* x          = (const float*)d_in[0];
    const float* inp_scale  = (const float*)d_in[1];
    const float* proj_in_w  = (const float*)d_in[2];
    const float* proj_in_b  = (const float*)d_in[3];
    const float* reup_w     = (const float*)d_in[4];
    const float* reup_b     = (const float*)d_in[5];
    const float* q_weights  = (const float*)d_in[6];
    const float* upload_sc  = (const float*)d_in[7];
    const float* meas_w     = (const float*)d_in[8];
    const float* proj_out_w = (const float*)d_in[9];
    const float* proj_out_b = (const float*)d_in[10];
    float* out = (float*)d_out;

    void *pxq, *pang, *pph, *ppl, *pxh, *pxl, *pwih, *pwil, *pwoh, *pwol;
    cudaGetSymbolAddress(&pxq,  g_xq);
    cudaGetSymbolAddress(&pang, g_ang);
    cudaGetSymbolAddress(&pph,  g_ph);
    cudaGetSymbolAddress(&ppl,  g_pl);
    cudaGetSymbolAddress(&pxh,  g_xh);
    cudaGetSymbolAddress(&pxl,  g_xl);
    cudaGetSymbolAddress(&pwih, g_wih);
    cudaGetSymbolAddress(&pwil, g_wil);
    cudaGetSymbolAddress(&pwoh, g_woh);
    cudaGetSymbolAddress(&pwol, g_wol);

    // dynamic SMEM: BK=64. BN=128 -> 2*73728=147456; BN=64 -> 2*55296=110592
    cudaFuncSetAttribute(mma_gemm<128>, cudaFuncAttributeMaxDynamicSharedMemorySize, 147456);
    cudaFuncSetAttribute(mma_gemm<64>,  cudaFuncAttributeMaxDynamicSharedMemorySize, 110592);

    // bf16 hi/lo splits (float4-vectorized)
    split_bf16v<<<(Bsz*INd/4 + 255)/256, 256>>>((const float4*)x, inp_scale,
        (__nv_bfloat162*)pxh, (__nv_bfloat162*)pxl, Bsz*INd/4);
    split_bf16v<<<(GQ*INd/4 + 255)/256, 256>>>((const float4*)proj_in_w, nullptr,
        (__nv_bfloat162*)pwih, (__nv_bfloat162*)pwil, GQ*INd/4);
    split_bf16v<<<(OUTd*GQ/4 + 255)/256, 256>>>((const float4*)proj_out_w, nullptr,
        (__nv_bfloat162*)pwoh, (__nv_bfloat162*)pwol, OUTd*GQ/4);

    // GEMM-in: xq[1024, 4096] = (x*scale) @ proj_in_w^T + b
    {
        dim3 grid(GQ/128, Bsz/128);
        mma_gemm<128><<<grid, 256, 147456>>>(Bsz, GQ, INd,
            (const __nv_bfloat16*)pxh, (const __nv_bfloat16*)pxl,
            (const __nv_bfloat16*)pwih, (const __nv_bfloat16*)pwil,
            proj_in_b, (float*)pxq);
    }

    // angles
    angles_kernel<<<Bsz, 320>>>(x, inp_scale, reup_w, reup_b, (float*)pang);

    // quantum circuit: 4096 states, one warp each -> probs (bf16 hi/lo)
    quantum_pk<<<1024, 128>>>((const float*)pxq, (const float*)pang,
        q_weights, upload_sc, meas_w,
        (__nv_bfloat16*)pph, (__nv_bfloat16*)ppl);

    // GEMM-out: out[1024, 1024] = probs @ proj_out_w^T + b
    {
        dim3 grid(OUTd/64, Bsz/128);
        mma_gemm<64><<<grid, 256, 110592>>>(Bsz, OUTd, GQ,
            (const __nv_bfloat16*)pph, (const __nv_bfloat16*)ppl,
            (const __nv_bfloat16*)pwoh, (const __nv_bfloat16*)pwol,
            proj_out_b, out);
    }
}

// round 10
// speedup vs baseline: 1.0215x; 1.0215x over previous
#include <cuda_runtime.h>
#include <cuda_bf16.h>
#include <math.h>
#include <cstdint>

#define Bsz  1024
#define INd  1024
#define OUTd 1024
#define NQw  10
#define Gg   4
#define DPT  4
#define QD   1024
#define GQ   4096   // G * QDIM

typedef unsigned long long u64;

// ---------------- scratch (device globals: no allocation allowed) ----------
__device__ float g_xq[Bsz * GQ];            // 16 MB (GEMM-in output, fp32)
__device__ float g_ang[Bsz * Gg * NQw];     // 160 KB
__device__ __nv_bfloat16 g_ph[Bsz * GQ];    // probs hi
__device__ __nv_bfloat16 g_pl[Bsz * GQ];    // probs lo
__device__ __nv_bfloat16 g_xh[Bsz * INd];   // (x*scale) hi
__device__ __nv_bfloat16 g_xl[Bsz * INd];
__device__ __nv_bfloat16 g_wih[GQ * INd];   // proj_in_w hi/lo
__device__ __nv_bfloat16 g_wil[GQ * INd];
__device__ __nv_bfloat16 g_woh[OUTd * GQ];  // proj_out_w hi/lo
__device__ __nv_bfloat16 g_wol[OUTd * GQ];

// ================= small PTX helpers (family-stable only; NO tcgen05) ======
__device__ __forceinline__ uint32_t smem_u32(const void* p){
    uint32_t a;
    asm("{ .reg .u64 t; cvta.to.shared.u64 t, %1; cvt.u32.u64 %0, t; }" : "=r"(a) : "l"(p));
    return a;
}
__device__ __forceinline__ void cp16(uint32_t s, const void* g){
    asm volatile("cp.async.cg.shared.global [%0], [%1], 16;" :: "r"(s), "l"(g) : "memory");
}
__device__ __forceinline__ void ldm4(uint32_t* r, uint32_t addr){
    asm volatile("ldmatrix.sync.aligned.m8n8.x4.shared.b16 {%0,%1,%2,%3}, [%4];"
                 : "=r"(r[0]), "=r"(r[1]), "=r"(r[2]), "=r"(r[3]) : "r"(addr));
}
__device__ __forceinline__ void mma_bf16(float* c, const uint32_t* a, const uint32_t* b){
    asm volatile(
        "mma.sync.aligned.m16n8k16.row.col.f32.bf16.bf16.f32 "
        "{%0,%1,%2,%3}, {%4,%5,%6,%7}, {%8,%9}, {%0,%1,%2,%3};"
        : "+f"(c[0]), "+f"(c[1]), "+f"(c[2]), "+f"(c[3])
        : "r"(a[0]), "r"(a[1]), "r"(a[2]), "r"(a[3]), "r"(b[0]), "r"(b[1]));
}

// ---- packed f32x2 (PTX ISA 8.6, sm_100+ family-generic) ----
__device__ __forceinline__ u64 f2fma(u64 a, u64 b, u64 c){
    u64 d; asm("fma.rn.f32x2 %0, %1, %2, %3;" : "=l"(d) : "l"(a), "l"(b), "l"(c)); return d;
}
__device__ __forceinline__ u64 f2mul(u64 a, u64 b){
    u64 d; asm("mul.rn.f32x2 %0, %1, %2;" : "=l"(d) : "l"(a), "l"(b)); return d;
}
__device__ __forceinline__ u64 pk2(float lo, float hi){
    u64 r;
    asm("mov.b64 %0, {%1, %2};" : "=l"(r) : "r"(__float_as_uint(lo)), "r"(__float_as_uint(hi)));
    return r;
}
__device__ __forceinline__ u64 dup2(float x){ return pk2(x, x); }
__device__ __forceinline__ void unpk(u64 v, float& a, float& b){
    uint32_t x, y;
    asm("mov.b64 {%0, %1}, %2;" : "=r"(x), "=r"(y) : "l"(v));
    a = __uint_as_float(x); b = __uint_as_float(y);
}
__device__ __forceinline__ u64 swp(u64 v){ float a, b; unpk(v, a, b); return pk2(b, a); }

// ================= bf16 split (hi + lo), float4-vectorized =================
__global__ void __launch_bounds__(256)
split_bf16v(const float4* __restrict__ src, const float* __restrict__ scale,
            __nv_bfloat162* __restrict__ hi, __nv_bfloat162* __restrict__ lo, int n4)
{
    int i = blockIdx.x * 256 + threadIdx.x;
    if (i < n4){
        float4 v = src[i];
        if (scale){
            int k = (4 * i) & (INd - 1);
            v.x *= scale[k]; v.y *= scale[k + 1]; v.z *= scale[k + 2]; v.w *= scale[k + 3];
        }
        __nv_bfloat16 hx = __float2bfloat16(v.x), hy = __float2bfloat16(v.y);
        __nv_bfloat16 hz = __float2bfloat16(v.z), hw = __float2bfloat16(v.w);
        hi[2 * i]     = __nv_bfloat162(hx, hy);
        hi[2 * i + 1] = __nv_bfloat162(hz, hw);
        lo[2 * i]     = __nv_bfloat162(__float2bfloat16(v.x - __bfloat162float(hx)),
                                       __float2bfloat16(v.y - __bfloat162float(hy)));
        lo[2 * i + 1] = __nv_bfloat162(__float2bfloat16(v.z - __bfloat162float(hz)),
                                       __float2bfloat16(v.w - __bfloat162float(hw)));
    }
}

// ================= HMMA GEMM: C[M,N] = Ahl[M,K] @ Bhl[N,K]^T + bias ========
// bf16x3 split: Ahi*Bhi + Ahi*Blo + Alo*Bhi, fp32 accum.
// CTA tile 128 x BN, BK=64, 8 warps (4m x 2n), warp tile 32 x (BN/2).
// 2-stage double buffer; prefetch after compute.
// SMEM rows: 64 bf16 data + 8 pad = 144B -> conflict-free ldmatrix + stores.
template<int BN>
__global__ void __launch_bounds__(256)
mma_gemm(int M, int N, int K,
         const __nv_bfloat16* __restrict__ Ahi, const __nv_bfloat16* __restrict__ Alo,
         const __nv_bfloat16* __restrict__ Bhi, const __nv_bfloat16* __restrict__ Blo,
         const float* __restrict__ bias, float* __restrict__ C)
{
    constexpr int A_BY = 128 * 144;       // 128 rows x 144B
    constexpr int B_BY = BN * 144;
    constexpr int STG_ = 2 * A_BY + 2 * B_BY;
    constexpr int NT   = BN / 16;         // n8 tiles per warp
    extern __shared__ char smc[];

    const int tid  = threadIdx.x;
    const int wid  = tid >> 5, lane = tid & 31;
    const int grp  = lane >> 2, tig = lane & 3;
    const int wm   = wid & 3,  wn = wid >> 2;       // 4 x 2 warp grid
    const int m0   = blockIdx.y * 128, n0 = blockIdx.x * BN;
    const uint32_t sb = smem_u32(smc);

    // ldmatrix lane-address components
    const int a_row = lane & 15, a_off = (lane >> 4) << 4;          // A .x4
    const int b_row = ((lane >> 4) << 3) + (lane & 7);              // B .x4 (2 tiles)
    const int b_off = ((lane >> 3) & 1) << 4;

    float c[2][NT][4];
#pragma unroll
    for (int mt = 0; mt < 2; mt++)
#pragma unroll
        for (int nt = 0; nt < NT; nt++)
#pragma unroll
            for (int q = 0; q < 4; q++) c[mt][nt][q] = 0.f;

    const int nk = K >> 6;                // K chunks of 64

    auto do_prefetch = [&](int i){
        const int st = i & 1;
        const int k0 = i << 6;
        const uint32_t ba = sb + st * STG_;
#pragma unroll
        for (int v = tid; v < 1024; v += 256){
            int r = v >> 3, ch = v & 7;
            uint32_t so = ba + r * 144 + ch * 16;
            cp16(so,        Ahi + (size_t)(m0 + r) * K + k0 + ch * 8);
            cp16(so + A_BY, Alo + (size_t)(m0 + r) * K + k0 + ch * 8);
        }
#pragma unroll
        for (int v = tid; v < BN * 8; v += 256){
            int r = v >> 3, ch = v & 7;
            uint32_t so = ba + 2 * A_BY + r * 144 + ch * 16;
            cp16(so,        Bhi + (size_t)(n0 + r) * K + k0 + ch * 8);
            cp16(so + B_BY, Blo + (size_t)(n0 + r) * K + k0 + ch * 8);
        }
        asm volatile("cp.async.commit_group;" ::: "memory");
    };

    do_prefetch(0);
    do_prefetch(1);

    for (int i = 0; i < nk; i++){
        if (i + 2 <= nk) asm volatile("cp.async.wait_group 1;" ::: "memory");
        else             asm volatile("cp.async.wait_group 0;" ::: "memory");
        __syncthreads();

        const uint32_t ba = sb + (i & 1) * STG_;
        const uint32_t bb = ba + 2 * A_BY;

#pragma unroll
        for (int kk = 0; kk < 4; kk++){
            uint32_t ah[2][4], al[2][4];
#pragma unroll
            for (int mt = 0; mt < 2; mt++){
                const uint32_t oa = ba + (wm * 32 + mt * 16 + a_row) * 144 + kk * 32 + a_off;
                ldm4(ah[mt], oa);
                ldm4(al[mt], oa + A_BY);
            }
            uint32_t bh[NT][2], bl[NT][2];
#pragma unroll
            for (int np = 0; np < NT / 2; np++){
                const uint32_t ob = bb + (wn * (NT * 8) + np * 16 + b_row) * 144 + kk * 32 + b_off;
                uint32_t t4[4];
                ldm4(t4, ob);
                bh[2*np][0] = t4[0]; bh[2*np][1] = t4[1];
                bh[2*np+1][0] = t4[2]; bh[2*np+1][1] = t4[3];
                ldm4(t4, ob + B_BY);
                bl[2*np][0] = t4[0]; bl[2*np][1] = t4[1];
                bl[2*np+1][0] = t4[2]; bl[2*np+1][1] = t4[3];
            }
#pragma unroll
            for (int mt = 0; mt < 2; mt++)
#pragma unroll
                for (int nt = 0; nt < NT; nt++){
                    mma_bf16(c[mt][nt], ah[mt], bh[nt]);
                    mma_bf16(c[mt][nt], ah[mt], bl[nt]);
                    mma_bf16(c[mt][nt], al[mt], bh[nt]);
                }
        }
        __syncthreads();
        if (i + 2 < nk) do_prefetch(i + 2);
    }

    // epilogue
#pragma unroll
    for (int mt = 0; mt < 2; mt++){
        const int row0 = m0 + wm * 32 + mt * 16 + grp;
#pragma unroll
        for (int nt = 0; nt < NT; nt++){
            const int col = n0 + wn * (NT * 8) + nt * 8 + 2 * tig;
            const float b0 = bias[col], b1 = bias[col + 1];
            float2 v0 = make_float2(c[mt][nt][0] + b0, c[mt][nt][1] + b1);
            float2 v1 = make_float2(c[mt][nt][2] + b0, c[mt][nt][3] + b1);
            *(float2*)&C[(size_t)row0       * N + col] = v0;
            *(float2*)&C[(size_t)(row0 + 8) * N + col] = v1;
        }
    }
}

// ---------------- angles: ang[b, j] = tanh((x*s) . reup_w[j] + reup_b[j]) * pi
__global__ void __launch_bounds__(320)
angles_kernel(const float* __restrict__ x, const float* __restrict__ inp_scale,
              const float* __restrict__ reup_w, const float* __restrict__ reup_b,
              float* __restrict__ ang)
{
    __shared__ float xs[INd];
    int b = blockIdx.x;
    for (int k = threadIdx.x; k < INd; k += blockDim.x)
        xs[k] = x[(size_t)b * INd + k] * inp_scale[k];
    __syncthreads();
    int warp = threadIdx.x >> 5, lane = threadIdx.x & 31;
#pragma unroll
    for (int q = 0; q < 4; q++){
        int j = warp * 4 + q;            // j in [0,40)
        const float* w = reup_w + (size_t)j * INd;
        float acc = 0.f;
        for (int k = lane; k < INd; k += 32) acc = fmaf(xs[k], w[k], acc);
#pragma unroll
        for (int o = 16; o; o >>= 1) acc += __shfl_xor_sync(0xffffffffu, acc, o);
        if (lane == 0)
            ang[(size_t)b * (Gg * NQw) + j] = tanhf(acc + reup_b[j]) * 3.14159265358979323846f;
    }
}

// ---------------- complex 2x2 helpers ----------------
struct C2 { float re, im; };
__device__ __forceinline__ C2 cmul(C2 a, C2 b){ return {a.re*b.re - a.im*b.im, a.re*b.im + a.im*b.re}; }
__device__ __forceinline__ C2 cadd(C2 a, C2 b){ return {a.re+b.re, a.im+b.im}; }
struct M2 { C2 m00, m01, m10, m11; };
__device__ __forceinline__ M2 mmul(M2 A, M2 B){  // A @ B
    M2 r;
    r.m00 = cadd(cmul(A.m00,B.m00), cmul(A.m01,B.m10));
    r.m01 = cadd(cmul(A.m00,B.m01), cmul(A.m01,B.m11));
    r.m10 = cadd(cmul(A.m10,B.m00), cmul(A.m11,B.m10));
    r.m11 = cadd(cmul(A.m10,B.m01), cmul(A.m11,B.m11));
    return r;
}
__device__ __forceinline__ M2 ry_m(float t){
    float c=cosf(0.5f*t), s=sinf(0.5f*t);
    return {{c,0.f},{-s,0.f},{s,0.f},{c,0.f}};
}
__device__ __forceinline__ M2 rx_m(float t){
    float c=cosf(0.5f*t), s=sinf(0.5f*t);
    return {{c,0.f},{0.f,-s},{0.f,-s},{c,0.f}};
}
__device__ __forceinline__ M2 u3_m(float t,float p,float l){
    float c=cosf(0.5f*t), s=sinf(0.5f*t);
    float cp=cosf(p), sp=sinf(p), cl=cosf(l), sl=sinf(l);
    M2 r;
    r.m00 = {c, 0.f};
    r.m01 = {-cl*s, -sl*s};
    r.m10 = {cp*s, sp*s};
    r.m11 = {(cp*cl - sp*sl)*c, (sp*cl + cp*sl)*c};
    return r;
}

// CNOT-ring permutation is XOR-linear: perm(a^b) = perm(a)^perm(b)
__device__ __forceinline__ int permL(int y){
#pragma unroll
    for (int k = 9; k >= 0; --k){
        int cb  = 9 - k;
        int tb2 = 9 - ((k + 1) % 10);
        y ^= ((y >> cb) & 1) << tb2;
    }
    return y;
}

// ================= quantum circuit: one WARP per (b,g) state ===============
// Lane l holds amps l*32+j (j=0..31), packed 2 amps per u64 over amp bit 0:
//   vr[k]/vi[k] = (re/im of amp l*32+2k, amp l*32+2k+1)
// Wires 0-4: lane-bit butterflies (shfl_xor, fully f32x2-vectorized).
// Wires 5-8: in-register pair-index butterflies (fully vectorized, no movs).
// Wire 9:    within-u64 butterfly (2 swaps per reg).
__global__ void __launch_bounds__(128)
quantum_pk(const float* __restrict__ xq, const float* __restrict__ ang,
           const float* __restrict__ qw, const float* __restrict__ us,
           const float* __restrict__ mw,
           __nv_bfloat16* __restrict__ ph, __nv_bfloat16* __restrict__ pl)
{
    __shared__ __align__(16) float ss[4][34 * 32];   // per-warp bounce (stride 34)
    const int wid = threadIdx.x >> 5, l = threadIdx.x & 31;
    const int s = blockIdx.x * 4 + wid;
    const int b = s >> 2, g = s & 3;
    const unsigned FULL = 0xffffffffu;
    float* buf = ss[wid];

    // permutation basis (constants per lane)
    const int zl  = permL(l << 5);
    const int B1  = permL(1), B2 = permL(2), B4 = permL(4), B8 = permL(8), B16 = permL(16);

    // ---- load (coalesced) -> transpose via smem -> packed registers ----
    const float* xrow = xq + (size_t)b * GQ + (size_t)g * QD;
#pragma unroll
    for (int j = 0; j < 32; j++) buf[j * 34 + l] = xrow[j * 32 + l];
    __syncwarp();
    u64 vr[16], vi[16];
    u64 acc2 = 0ull;
#pragma unroll
    for (int k = 0; k < 16; k++){
        vr[k] = *(const u64*)&buf[l * 34 + 2 * k];
        acc2  = f2fma(vr[k], vr[k], acc2);
        vi[k] = 0ull;
    }
    float na, nb; unpk(acc2, na, nb);
    float nrm = na + nb;
#pragma unroll
    for (int o = 16; o; o >>= 1) nrm += __shfl_xor_sync(FULL, nrm, o);
    const u64 iv = dup2(1.0f / (sqrtf(nrm) + 1e-9f));
#pragma unroll
    for (int k = 0; k < 16; k++) vr[k] = f2mul(iv, vr[k]);
    __syncwarp();

    for (int r = 0; r < 5; r++){
        // ---- lanes 0..9 build fused 2x2 gate matrix for wire l ----
        float m0=0,m1=0,m2=0,m3=0,m4=0,m5=0,m6=0,m7=0;
        if (l < NQw){
            const int i = l;
            M2 M;
            if (r < 4){
                float a = ang[(size_t)b * (Gg * NQw) + g * NQw + i];
                float theta = a * us[(g * DPT + r) * NQw + i];
                if (r > 0) theta += qw[((g * DPT + (r - 1)) * NQw + i) * 3 + 2];
                const float* q = qw + ((size_t)(g * DPT + r) * NQw + i) * 3;
                M = mmul(ry_m(q[1]), mmul(rx_m(q[0]), ry_m(theta)));
            } else {
                const float* m = mw + ((size_t)g * NQw + i) * 3;
                float t2 = qw[((g * DPT + 3) * NQw + i) * 3 + 2];
                M = mmul(u3_m(m[0], m[1], m[2]), ry_m(t2));
            }
            m0=M.m00.re; m1=M.m00.im; m2=M.m01.re; m3=M.m01.im;
            m4=M.m10.re; m5=M.m10.im; m6=M.m11.re; m7=M.m11.im;
        }

        // ---- wires 0..4: lane-bit butterflies ----
#pragma unroll
        for (int i = 0; i < 5; i++){
            const float c0=__shfl_sync(FULL,m0,i), c1=__shfl_sync(FULL,m1,i);
            const float c2=__shfl_sync(FULL,m2,i), c3=__shfl_sync(FULL,m3,i);
            const float c4=__shfl_sync(FULL,m4,i), c5=__shfl_sync(FULL,m5,i);
            const float c6=__shfl_sync(FULL,m6,i), c7=__shfl_sync(FULL,m7,i);
            const int lb = 4 - i, msk = 1 << lb;
            const bool hb = (l >> lb) & 1;
            const float aR = hb ? c6 : c0, aI = hb ? c7 : c1;   // m11 : m00
            const float bR = hb ? c4 : c2, bI = hb ? c5 : c3;   // m10 : m01
            const u64 PaR = dup2(aR), NaI = dup2(-aI), QaI = dup2(aI);
            const u64 PbR = dup2(bR), NbI = dup2(-bI), QbI = dup2(bI);
#pragma unroll
            for (int k = 0; k < 16; k++){
                u64 pr  = __shfl_xor_sync(FULL, vr[k], msk);
                u64 pim = __shfl_xor_sync(FULL, vi[k], msk);
                u64 orr = vr[k], oii = vi[k];
                vr[k] = f2fma(PaR, orr, f2fma(NaI, oii, f2fma(PbR, pr,  f2mul(NbI, pim))));
                vi[k] = f2fma(PaR, oii, f2fma(QaI, orr, f2fma(PbR, pim, f2mul(QbI, pr))));
            }
        }

        // ---- wires 5..8: in-register pair-index butterflies ----
#pragma unroll
        for (int w = 5; w <= 8; w++){
            const float c0=__shfl_sync(FULL,m0,w), c1=__shfl_sync(FULL,m1,w);
            const float c2=__shfl_sync(FULL,m2,w), c3=__shfl_sync(FULL,m3,w);
            const float c4=__shfl_sync(FULL,m4,w), c5=__shfl_sync(FULL,m5,w);
            const float c6=__shfl_sync(FULL,m6,w), c7=__shfl_sync(FULL,m7,w);
            const u64 Pr00=dup2(c0), Ni00=dup2(-c1), Qi00=dup2(c1);
            const u64 Pr01=dup2(c2), Ni01=dup2(-c3), Qi01=dup2(c3);
            const u64 Pr10=dup2(c4), Ni10=dup2(-c5), Qi10=dup2(c5);
            const u64 Pr11=dup2(c6), Ni11=dup2(-c7), Qi11=dup2(c7);
            const int SBc = 8 - w;               // pair-index bit
#pragma unroll
            for (int kk = 0; kk < 8; kk++){
                const int k0 = ((kk >> SBc) << (SBc + 1)) | (kk & ((1 << SBc) - 1));
                const int k1 = k0 | (1 << SBc);
                u64 a0r = vr[k0], a0i = vi[k0], a1r = vr[k1], a1i = vi[k1];
                vr[k0] = f2fma(Pr00, a0r, f2fma(Ni00, a0i, f2fma(Pr01, a1r, f2mul(Ni01, a1i))));
                vi[k0] = f2fma(Pr00, a0i, f2fma(Qi00, a0r, f2fma(Pr01, a1i, f2mul(Qi01, a1r))));
                vr[k1] = f2fma(Pr10, a0r, f2fma(Ni10, a0i, f2fma(Pr11, a1r, f2mul(Ni11, a1i))));
                vi[k1] = f2fma(Pr10, a0i, f2fma(Qi10, a0r, f2fma(Pr11, a1i, f2mul(Qi11, a1r))));
            }
        }

        // ---- wire 9: within-u64 butterfly ----
        {
            const float c0=__shfl_sync(FULL,m0,9), c1=__shfl_sync(FULL,m1,9);
            const float c2=__shfl_sync(FULL,m2,9), c3=__shfl_sync(FULL,m3,9);
            const float c4=__shfl_sync(FULL,m4,9), c5=__shfl_sync(FULL,m5,9);
            const float c6=__shfl_sync(FULL,m6,9), c7=__shfl_sync(FULL,m7,9);
            const u64 P1 = pk2(c0, c6),  P2 = pk2(c2, c4);
            const u64 N1 = pk2(-c1, -c7), N2 = pk2(-c3, -c5);
            const u64 Q1 = pk2(c1, c7),  Q2 = pk2(c3, c5);
#pragma unroll
            for (int k = 0; k < 16; k++){
                u64 xr = vr[k], xi_ = vi[k];
                u64 xsr = swp(xr), xsi = swp(xi_);
                vr[k] = f2fma(P1, xr,  f2fma(P2, xsr, f2fma(N1, xi_, f2mul(N2, xsi))));
                vi[k] = f2fma(P1, xi_, f2fma(P2, xsi, f2fma(Q1, xr,  f2mul(Q2, xsr))));
            }
        }

        // ---- CNOT-ring permutation (rounds 0..3) via smem, XOR-linear ----
        if (r < 4){
            __syncwarp();
            u64 tr[16];
#pragma unroll
            for (int k = 0; k < 16; k++) *(u64*)&buf[l * 34 + 2 * k] = vr[k];
            __syncwarp();
#pragma unroll
            for (int k = 0; k < 16; k++){
                const int j0 = 2 * k, j1 = 2 * k + 1;
                const int zj0 = ((j0&1)?B1:0) ^ ((j0&2)?B2:0) ^ ((j0&4)?B4:0) ^ ((j0&8)?B8:0) ^ ((j0&16)?B16:0);
                const int zj1 = zj0 ^ B1;        // j1 = j0 ^ 1
                const int z0 = zl ^ zj0, z1 = zl ^ zj1;
                tr[k] = pk2(buf[(z0 >> 5) * 34 + (z0 & 31)],
                            buf[(z1 >> 5) * 34 + (z1 & 31)]);
            }
            __syncwarp();
#pragma unroll
            for (int k = 0; k < 16; k++) *(u64*)&buf[l * 34 + 2 * k] = vi[k];
            __syncwarp();
#pragma unroll
            for (int k = 0; k < 16; k++){
                const int j0 = 2 * k, j1 = 2 * k + 1;
                const int zj0 = ((j0&1)?B1:0) ^ ((j0&2)?B2:0) ^ ((j0&4)?B4:0) ^ ((j0&8)?B8:0) ^ ((j0&16)?B16:0);
                const int zj1 = zj0 ^ B1;
                const int z0 = zl ^ zj0, z1 = zl ^ zj1;
                vi[k] = pk2(buf[(z0 >> 5) * 34 + (z0 & 31)],
                            buf[(z1 >> 5) * 34 + (z1 & 31)]);
                vr[k] = tr[k];
            }
            __syncwarp();
        }
    }

    // ---- probabilities: packed square-sum, transpose, bf16 hi/lo store ----
    __syncwarp();
#pragma unroll
    for (int k = 0; k < 16; k++)
        *(u64*)&buf[l * 34 + 2 * k] = f2fma(vr[k], vr[k], f2mul(vi[k], vi[k]));
    __syncwarp();
    const size_t o = (size_t)b * GQ + (size_t)g * QD;
#pragma unroll
    for (int j = 0; j < 32; j++){
        float p = buf[j * 34 + l];
        __nv_bfloat16 h = __float2bfloat16(p);
        ph[o + j * 32 + l] = h;
        pl[o + j * 32 + l] = __float2bfloat16(p - __bfloat162float(h));
    }
}

// ---------------- launch ----------------
extern "C" void kernel_launch(void* const* d_in, const int* in_sizes, int n_in,
                              void* d_out, int out_size)
{
    const float* x          = (const float*)d_in[0];
    const float* inp_scale  = (const float*)d_in[1];
    const float* proj_in_w  = (const float*)d_in[2];
    const float* proj_in_b  = (const float*)d_in[3];
    const float* reup_w     = (const float*)d_in[4];
    const float* reup_b     = (const float*)d_in[5];
    const float* q_weights  = (const float*)d_in[6];
    const float* upload_sc  = (const float*)d_in[7];
    const float* meas_w     = (const float*)d_in[8];
    const float* proj_out_w = (const float*)d_in[9];
    const float* proj_out_b = (const float*)d_in[10];
    float* out = (float*)d_out;

    void *pxq, *pang, *pph, *ppl, *pxh, *pxl, *pwih, *pwil, *pwoh, *pwol;
    cudaGetSymbolAddress(&pxq,  g_xq);
    cudaGetSymbolAddress(&pang, g_ang);
    cudaGetSymbolAddress(&pph,  g_ph);
    cudaGetSymbolAddress(&ppl,  g_pl);
    cudaGetSymbolAddress(&pxh,  g_xh);
    cudaGetSymbolAddress(&pxl,  g_xl);
    cudaGetSymbolAddress(&pwih, g_wih);
    cudaGetSymbolAddress(&pwil, g_wil);
    cudaGetSymbolAddress(&pwoh, g_woh);
    cudaGetSymbolAddress(&pwol, g_wol);

    // dynamic SMEM: BK=64. BN=128 -> 2*73728=147456; BN=64 -> 2*55296=110592
    cudaFuncSetAttribute(mma_gemm<128>, cudaFuncAttributeMaxDynamicSharedMemorySize, 147456);
    cudaFuncSetAttribute(mma_gemm<64>,  cudaFuncAttributeMaxDynamicSharedMemorySize, 110592);

    // ---- side streams + events (created once, on the uncaptured correctness
    // call; captured calls perform identical launches/edges every time) ----
    static cudaStream_t s1 = nullptr, s2 = nullptr;
    static cudaEvent_t ev_fork = nullptr, ev_wi = nullptr, ev_wo = nullptr;
    if (!ev_fork){
        if (cudaStreamCreateWithFlags(&s1, cudaStreamNonBlocking) != cudaSuccess) s1 = nullptr;
        if (cudaStreamCreateWithFlags(&s2, cudaStreamNonBlocking) != cudaSuccess) s2 = nullptr;
        cudaEventCreateWithFlags(&ev_fork, cudaEventDisableTiming);
        cudaEventCreateWithFlags(&ev_wi,   cudaEventDisableTiming);
        cudaEventCreateWithFlags(&ev_wo,   cudaEventDisableTiming);
    }
    const cudaStream_t S1 = s1 ? s1 : (cudaStream_t)0;
    const cudaStream_t S2 = s2 ? s2 : (cudaStream_t)0;

    // fork: weight splits run on side streams, overlapped with main chain
    cudaEventRecord(ev_fork, 0);
    cudaStreamWaitEvent(S1, ev_fork, 0);
    cudaStreamWaitEvent(S2, ev_fork, 0);

    // wi-split (needed by GEMM-in) on S1
    split_bf16v<<<(GQ*INd/4 + 255)/256, 256, 0, S1>>>((const float4*)proj_in_w, nullptr,
        (__nv_bfloat162*)pwih, (__nv_bfloat162*)pwil, GQ*INd/4);
    cudaEventRecord(ev_wi, S1);

    // wo-split (needed by GEMM-out) on S2
    split_bf16v<<<(OUTd*GQ/4 + 255)/256, 256, 0, S2>>>((const float4*)proj_out_w, nullptr,
        (__nv_bfloat162*)pwoh, (__nv_bfloat162*)pwol, OUTd*GQ/4);
    cudaEventRecord(ev_wo, S2);

    // main chain: x-split, angles
    split_bf16v<<<(Bsz*INd/4 + 255)/256, 256>>>((const float4*)x, inp_scale,
        (__nv_bfloat162*)pxh, (__nv_bfloat162*)pxl, Bsz*INd/4);
    angles_kernel<<<Bsz, 320>>>(x, inp_scale, reup_w, reup_b, (float*)pang);

    // join wi -> GEMM-in
    cudaStreamWaitEvent((cudaStream_t)0, ev_wi, 0);
    {
        dim3 grid(GQ/128, Bsz/128);
        mma_gemm<128><<<grid, 256, 147456>>>(Bsz, GQ, INd,
            (const __nv_bfloat16*)pxh, (const __nv_bfloat16*)pxl,
            (const __nv_bfloat16*)pwih, (const __nv_bfloat16*)pwil,
            proj_in_b, (float*)pxq);
    }

    // quantum circuit: 4096 states, one warp each -> probs (bf16 hi/lo)
    quantum_pk<<<1024, 128>>>((const float*)pxq, (const float*)pang,
        q_weights, upload_sc, meas_w,
        (__nv_bfloat16*)pph, (__nv_bfloat16*)ppl);

    // join wo -> GEMM-out
    cudaStreamWaitEvent((cudaStream_t)0, ev_wo, 0);
    {
        dim3 grid(OUTd/64, Bsz/128);
        mma_gemm<64><<<grid, 256, 110592>>>(Bsz, OUTd, GQ,
            (const __nv_bfloat16*)pph, (const __nv_bfloat16*)ppl,
            (const __nv_bfloat16*)pwoh, (const __nv_bfloat16*)pwol,
            proj_out_b, out);
    }
}

// round 12
// speedup vs baseline: 1.0292x; 1.0076x over previous
#include <cuda_runtime.h>
#include <cuda_bf16.h>
#include <math.h>
#include <cstdint>

#define Bsz  1024
#define INd  1024
#define OUTd 1024
#define NQw  10
#define Gg   4
#define DPT  4
#define QD   1024
#define GQ   4096   // G * QDIM

typedef unsigned long long u64;

// ---------------- scratch (device globals: no allocation allowed) ----------
__device__ float g_xq[Bsz * GQ];            // 16 MB (GEMM-in output, fp32)
__device__ float g_ang[Bsz * Gg * NQw];     // 160 KB
__device__ __nv_bfloat16 g_ph[Bsz * GQ];    // probs hi
__device__ __nv_bfloat16 g_pl[Bsz * GQ];    // probs lo
__device__ __nv_bfloat16 g_xh[Bsz * INd];   // (x*scale) hi
__device__ __nv_bfloat16 g_xl[Bsz * INd];
__device__ __nv_bfloat16 g_wih[GQ * INd];   // proj_in_w hi/lo
__device__ __nv_bfloat16 g_wil[GQ * INd];
__device__ __nv_bfloat16 g_woh[OUTd * GQ];  // proj_out_w hi/lo
__device__ __nv_bfloat16 g_wol[OUTd * GQ];

// ================= small PTX helpers (family-stable only; NO tcgen05) ======
__device__ __forceinline__ uint32_t smem_u32(const void* p){
    uint32_t a;
    asm("{ .reg .u64 t; cvta.to.shared.u64 t, %1; cvt.u32.u64 %0, t; }" : "=r"(a) : "l"(p));
    return a;
}
__device__ __forceinline__ void cp16(uint32_t s, const void* g){
    asm volatile("cp.async.cg.shared.global [%0], [%1], 16;" :: "r"(s), "l"(g) : "memory");
}
__device__ __forceinline__ void ldm4(uint32_t* r, uint32_t addr){
    asm volatile("ldmatrix.sync.aligned.m8n8.x4.shared.b16 {%0,%1,%2,%3}, [%4];"
                 : "=r"(r[0]), "=r"(r[1]), "=r"(r[2]), "=r"(r[3]) : "r"(addr));
}
__device__ __forceinline__ void mma_bf16(float* c, const uint32_t* a, const uint32_t* b){
    asm volatile(
        "mma.sync.aligned.m16n8k16.row.col.f32.bf16.bf16.f32 "
        "{%0,%1,%2,%3}, {%4,%5,%6,%7}, {%8,%9}, {%0,%1,%2,%3};"
        : "+f"(c[0]), "+f"(c[1]), "+f"(c[2]), "+f"(c[3])
        : "r"(a[0]), "r"(a[1]), "r"(a[2]), "r"(a[3]), "r"(b[0]), "r"(b[1]));
}

// ---- packed f32x2 (PTX ISA 8.6, sm_100+ family-generic) ----
__device__ __forceinline__ u64 f2fma(u64 a, u64 b, u64 c){
    u64 d; asm("fma.rn.f32x2 %0, %1, %2, %3;" : "=l"(d) : "l"(a), "l"(b), "l"(c)); return d;
}
__device__ __forceinline__ u64 f2mul(u64 a, u64 b){
    u64 d; asm("mul.rn.f32x2 %0, %1, %2;" : "=l"(d) : "l"(a), "l"(b)); return d;
}
__device__ __forceinline__ u64 pk2(float lo, float hi){
    u64 r;
    asm("mov.b64 %0, {%1, %2};" : "=l"(r) : "r"(__float_as_uint(lo)), "r"(__float_as_uint(hi)));
    return r;
}
__device__ __forceinline__ u64 dup2(float x){ return pk2(x, x); }
__device__ __forceinline__ void unpk(u64 v, float& a, float& b){
    uint32_t x, y;
    asm("mov.b64 {%0, %1}, %2;" : "=r"(x), "=r"(y) : "l"(v));
    a = __uint_as_float(x); b = __uint_as_float(y);
}
__device__ __forceinline__ u64 swp(u64 v){ float a, b; unpk(v, a, b); return pk2(b, a); }

// ================= bf16 split (hi + lo), float4-vectorized =================
__global__ void __launch_bounds__(256)
split_bf16v(const float4* __restrict__ src, const float* __restrict__ scale,
            __nv_bfloat162* __restrict__ hi, __nv_bfloat162* __restrict__ lo, int n4)
{
    int i = blockIdx.x * 256 + threadIdx.x;
    if (i < n4){
        float4 v = src[i];
        if (scale){
            int k = (4 * i) & (INd - 1);
            v.x *= scale[k]; v.y *= scale[k + 1]; v.z *= scale[k + 2]; v.w *= scale[k + 3];
        }
        __nv_bfloat16 hx = __float2bfloat16(v.x), hy = __float2bfloat16(v.y);
        __nv_bfloat16 hz = __float2bfloat16(v.z), hw = __float2bfloat16(v.w);
        hi[2 * i]     = __nv_bfloat162(hx, hy);
        hi[2 * i + 1] = __nv_bfloat162(hz, hw);
        lo[2 * i]     = __nv_bfloat162(__float2bfloat16(v.x - __bfloat162float(hx)),
                                       __float2bfloat16(v.y - __bfloat162float(hy)));
        lo[2 * i + 1] = __nv_bfloat162(__float2bfloat16(v.z - __bfloat162float(hz)),
                                       __float2bfloat16(v.w - __bfloat162float(hw)));
    }
}

// ================= HMMA GEMM: C[M,N] = Ahl[M,K] @ Bhl[N,K]^T + bias ========
// bf16x3 split: Ahi*Bhi + Ahi*Blo + Alo*Bhi, fp32 accum.
// CTA tile 128 x BN, BK=64, 8 warps (4m x 2n), warp tile 32 x (BN/2).
// 2-stage double buffer; prefetch after compute.
// SMEM rows: 64 bf16 data + 8 pad = 144B -> conflict-free ldmatrix + stores.
template<int BN>
__global__ void __launch_bounds__(256)
mma_gemm(int M, int N, int K,
         const __nv_bfloat16* __restrict__ Ahi, const __nv_bfloat16* __restrict__ Alo,
         const __nv_bfloat16* __restrict__ Bhi, const __nv_bfloat16* __restrict__ Blo,
         const float* __restrict__ bias, float* __restrict__ C)
{
    constexpr int A_BY = 128 * 144;       // 128 rows x 144B
    constexpr int B_BY = BN * 144;
    constexpr int STG_ = 2 * A_BY + 2 * B_BY;
    constexpr int NT   = BN / 16;         // n8 tiles per warp
    extern __shared__ char smc[];

    const int tid  = threadIdx.x;
    const int wid  = tid >> 5, lane = tid & 31;
    const int grp  = lane >> 2, tig = lane & 3;
    const int wm   = wid & 3,  wn = wid >> 2;       // 4 x 2 warp grid
    const int m0   = blockIdx.y * 128, n0 = blockIdx.x * BN;
    const uint32_t sb = smem_u32(smc);

    // ldmatrix lane-address components
    const int a_row = lane & 15, a_off = (lane >> 4) << 4;          // A .x4
    const int b_row = ((lane >> 4) << 3) + (lane & 7);              // B .x4 (2 tiles)
    const int b_off = ((lane >> 3) & 1) << 4;

    float c[2][NT][4];
#pragma unroll
    for (int mt = 0; mt < 2; mt++)
#pragma unroll
        for (int nt = 0; nt < NT; nt++)
#pragma unroll
            for (int q = 0; q < 4; q++) c[mt][nt][q] = 0.f;

    const int nk = K >> 6;                // K chunks of 64

    auto do_prefetch = [&](int i){
        const int st = i & 1;
        const int k0 = i << 6;
        const uint32_t ba = sb + st * STG_;
#pragma unroll
        for (int v = tid; v < 1024; v += 256){
            int r = v >> 3, ch = v & 7;
            uint32_t so = ba + r * 144 + ch * 16;
            cp16(so,        Ahi + (size_t)(m0 + r) * K + k0 + ch * 8);
            cp16(so + A_BY, Alo + (size_t)(m0 + r) * K + k0 + ch * 8);
        }
#pragma unroll
        for (int v = tid; v < BN * 8; v += 256){
            int r = v >> 3, ch = v & 7;
            uint32_t so = ba + 2 * A_BY + r * 144 + ch * 16;
            cp16(so,        Bhi + (size_t)(n0 + r) * K + k0 + ch * 8);
            cp16(so + B_BY, Blo + (size_t)(n0 + r) * K + k0 + ch * 8);
        }
        asm volatile("cp.async.commit_group;" ::: "memory");
    };

    do_prefetch(0);
    do_prefetch(1);

    for (int i = 0; i < nk; i++){
        if (i + 2 <= nk) asm volatile("cp.async.wait_group 1;" ::: "memory");
        else             asm volatile("cp.async.wait_group 0;" ::: "memory");
        __syncthreads();

        const uint32_t ba = sb + (i & 1) * STG_;
        const uint32_t bb = ba + 2 * A_BY;

#pragma unroll
        for (int kk = 0; kk < 4; kk++){
            uint32_t ah[2][4], al[2][4];
#pragma unroll
            for (int mt = 0; mt < 2; mt++){
                const uint32_t oa = ba + (wm * 32 + mt * 16 + a_row) * 144 + kk * 32 + a_off;
                ldm4(ah[mt], oa);
                ldm4(al[mt], oa + A_BY);
            }
            uint32_t bh[NT][2], bl[NT][2];
#pragma unroll
            for (int np = 0; np < NT / 2; np++){
                const uint32_t ob = bb + (wn * (NT * 8) + np * 16 + b_row) * 144 + kk * 32 + b_off;
                uint32_t t4[4];
                ldm4(t4, ob);
                bh[2*np][0] = t4[0]; bh[2*np][1] = t4[1];
                bh[2*np+1][0] = t4[2]; bh[2*np+1][1] = t4[3];
                ldm4(t4, ob + B_BY);
                bl[2*np][0] = t4[0]; bl[2*np][1] = t4[1];
                bl[2*np+1][0] = t4[2]; bl[2*np+1][1] = t4[3];
            }
#pragma unroll
            for (int mt = 0; mt < 2; mt++)
#pragma unroll
                for (int nt = 0; nt < NT; nt++){
                    mma_bf16(c[mt][nt], ah[mt], bh[nt]);
                    mma_bf16(c[mt][nt], ah[mt], bl[nt]);
                    mma_bf16(c[mt][nt], al[mt], bh[nt]);
                }
        }
        __syncthreads();
        if (i + 2 < nk) do_prefetch(i + 2);
    }

    // epilogue
#pragma unroll
    for (int mt = 0; mt < 2; mt++){
        const int row0 = m0 + wm * 32 + mt * 16 + grp;
#pragma unroll
        for (int nt = 0; nt < NT; nt++){
            const int col = n0 + wn * (NT * 8) + nt * 8 + 2 * tig;
            const float b0 = bias[col], b1 = bias[col + 1];
            float2 v0 = make_float2(c[mt][nt][0] + b0, c[mt][nt][1] + b1);
            float2 v1 = make_float2(c[mt][nt][2] + b0, c[mt][nt][3] + b1);
            *(float2*)&C[(size_t)row0       * N + col] = v0;
            *(float2*)&C[(size_t)(row0 + 8) * N + col] = v1;
        }
    }
}

// ---------------- angles: ang[b, j] = tanh((x*s) . reup_w[j] + reup_b[j]) * pi
__global__ void __launch_bounds__(320)
angles_kernel(const float* __restrict__ x, const float* __restrict__ inp_scale,
              const float* __restrict__ reup_w, const float* __restrict__ reup_b,
              float* __restrict__ ang)
{
    __shared__ float xs[INd];
    int b = blockIdx.x;
    for (int k = threadIdx.x; k < INd; k += blockDim.x)
        xs[k] = x[(size_t)b * INd + k] * inp_scale[k];
    __syncthreads();
    int warp = threadIdx.x >> 5, lane = threadIdx.x & 31;
#pragma unroll
    for (int q = 0; q < 4; q++){
        int j = warp * 4 + q;            // j in [0,40)
        const float* w = reup_w + (size_t)j * INd;
        float acc = 0.f;
        for (int k = lane; k < INd; k += 32) acc = fmaf(xs[k], w[k], acc);
#pragma unroll
        for (int o = 16; o; o >>= 1) acc += __shfl_xor_sync(0xffffffffu, acc, o);
        if (lane == 0)
            ang[(size_t)b * (Gg * NQw) + j] = tanhf(acc + reup_b[j]) * 3.14159265358979323846f;
    }
}

// ---------------- complex 2x2 helpers ----------------
struct C2 { float re, im; };
__device__ __forceinline__ C2 cmul(C2 a, C2 b){ return {a.re*b.re - a.im*b.im, a.re*b.im + a.im*b.re}; }
__device__ __forceinline__ C2 cadd(C2 a, C2 b){ return {a.re+b.re, a.im+b.im}; }
struct M2 { C2 m00, m01, m10, m11; };
__device__ __forceinline__ M2 mmul(M2 A, M2 B){  // A @ B
    M2 r;
    r.m00 = cadd(cmul(A.m00,B.m00), cmul(A.m01,B.m10));
    r.m01 = cadd(cmul(A.m00,B.m01), cmul(A.m01,B.m11));
    r.m10 = cadd(cmul(A.m10,B.m00), cmul(A.m11,B.m10));
    r.m11 = cadd(cmul(A.m10,B.m01), cmul(A.m11,B.m11));
    return r;
}
__device__ __forceinline__ M2 ry_m(float t){
    float c=cosf(0.5f*t), s=sinf(0.5f*t);
    return {{c,0.f},{-s,0.f},{s,0.f},{c,0.f}};
}
__device__ __forceinline__ M2 rx_m(float t){
    float c=cosf(0.5f*t), s=sinf(0.5f*t);
    return {{c,0.f},{0.f,-s},{0.f,-s},{c,0.f}};
}
__device__ __forceinline__ M2 u3_m(float t,float p,float l){
    float c=cosf(0.5f*t), s=sinf(0.5f*t);
    float cp=cosf(p), sp=sinf(p), cl=cosf(l), sl=sinf(l);
    M2 r;
    r.m00 = {c, 0.f};
    r.m01 = {-cl*s, -sl*s};
    r.m10 = {cp*s, sp*s};
    r.m11 = {(cp*cl - sp*sl)*c, (sp*cl + cp*sl)*c};
    return r;
}

// CNOT-ring permutation is XOR-linear: perm(a^b) = perm(a)^perm(b)
__device__ __forceinline__ int permL(int y){
#pragma unroll
    for (int k = 9; k >= 0; --k){
        int cb  = 9 - k;
        int tb2 = 9 - ((k + 1) % 10);
        y ^= ((y >> cb) & 1) << tb2;
    }
    return y;
}

// ================= quantum circuit: one WARP per (b,g) state ===============
// Lane l holds amps l*32+j (j=0..31), packed 2 amps per u64 over amp bit 0:
//   vr[k]/vi[k] = (re/im of amp l*32+2k, amp l*32+2k+1)
// Wires 0-4: lane-bit butterflies (shfl_xor, fully f32x2-vectorized).
// Wires 5-8: in-register pair-index butterflies (fully vectorized, no movs).
// Wire 9:    within-u64 butterfly (2 swaps per reg).
__global__ void __launch_bounds__(128)
quantum_pk(const float* __restrict__ xq, const float* __restrict__ ang,
           const float* __restrict__ qw, const float* __restrict__ us,
           const float* __restrict__ mw,
           __nv_bfloat16* __restrict__ ph, __nv_bfloat16* __restrict__ pl)
{
    __shared__ __align__(16) float ss[4][34 * 32];   // per-warp bounce (stride 34)
    const int wid = threadIdx.x >> 5, l = threadIdx.x & 31;
    const int s = blockIdx.x * 4 + wid;
    const int b = s >> 2, g = s & 3;
    const unsigned FULL = 0xffffffffu;
    float* buf = ss[wid];

    // permutation basis (constants per lane)
    const int zl  = permL(l << 5);
    const int B1  = permL(1), B2 = permL(2), B4 = permL(4), B8 = permL(8), B16 = permL(16);

    // ---- load (coalesced) -> transpose via smem -> packed registers ----
    const float* xrow = xq + (size_t)b * GQ + (size_t)g * QD;
#pragma unroll
    for (int j = 0; j < 32; j++) buf[j * 34 + l] = xrow[j * 32 + l];
    __syncwarp();
    u64 vr[16], vi[16];
    u64 acc2 = 0ull;
#pragma unroll
    for (int k = 0; k < 16; k++){
        vr[k] = *(const u64*)&buf[l * 34 + 2 * k];
        acc2  = f2fma(vr[k], vr[k], acc2);
        vi[k] = 0ull;
    }
    float na, nb; unpk(acc2, na, nb);
    float nrm = na + nb;
#pragma unroll
    for (int o = 16; o; o >>= 1) nrm += __shfl_xor_sync(FULL, nrm, o);
    const u64 iv = dup2(1.0f / (sqrtf(nrm) + 1e-9f));
#pragma unroll
    for (int k = 0; k < 16; k++) vr[k] = f2mul(iv, vr[k]);
    __syncwarp();

    for (int r = 0; r < 5; r++){
        // ---- lanes 0..9 build fused 2x2 gate matrix for wire l ----
        float m0=0,m1=0,m2=0,m3=0,m4=0,m5=0,m6=0,m7=0;
        if (l < NQw){
            const int i = l;
            M2 M;
            if (r < 4){
                float a = ang[(size_t)b * (Gg * NQw) + g * NQw + i];
                float theta = a * us[(g * DPT + r) * NQw + i];
                if (r > 0) theta += qw[((g * DPT + (r - 1)) * NQw + i) * 3 + 2];
                const float* q = qw + ((size_t)(g * DPT + r) * NQw + i) * 3;
                M = mmul(ry_m(q[1]), mmul(rx_m(q[0]), ry_m(theta)));
            } else {
                const float* m = mw + ((size_t)g * NQw + i) * 3;
                float t2 = qw[((g * DPT + 3) * NQw + i) * 3 + 2];
                M = mmul(u3_m(m[0], m[1], m[2]), ry_m(t2));
            }
            m0=M.m00.re; m1=M.m00.im; m2=M.m01.re; m3=M.m01.im;
            m4=M.m10.re; m5=M.m10.im; m6=M.m11.re; m7=M.m11.im;
        }

        // ---- wires 0..4: lane-bit butterflies ----
#pragma unroll
        for (int i = 0; i < 5; i++){
            const float c0=__shfl_sync(FULL,m0,i), c1=__shfl_sync(FULL,m1,i);
            const float c2=__shfl_sync(FULL,m2,i), c3=__shfl_sync(FULL,m3,i);
            const float c4=__shfl_sync(FULL,m4,i), c5=__shfl_sync(FULL,m5,i);
            const float c6=__shfl_sync(FULL,m6,i), c7=__shfl_sync(FULL,m7,i);
            const int lb = 4 - i, msk = 1 << lb;
            const bool hb = (l >> lb) & 1;
            const float aR = hb ? c6 : c0, aI = hb ? c7 : c1;   // m11 : m00
            const float bR = hb ? c4 : c2, bI = hb ? c5 : c3;   // m10 : m01
            const u64 PaR = dup2(aR), NaI = dup2(-aI), QaI = dup2(aI);
            const u64 PbR = dup2(bR), NbI = dup2(-bI), QbI = dup2(bI);
#pragma unroll
            for (int k = 0; k < 16; k++){
                u64 pr  = __shfl_xor_sync(FULL, vr[k], msk);
                u64 pim = __shfl_xor_sync(FULL, vi[k], msk);
                u64 orr = vr[k], oii = vi[k];
                vr[k] = f2fma(PaR, orr, f2fma(NaI, oii, f2fma(PbR, pr,  f2mul(NbI, pim))));
                vi[k] = f2fma(PaR, oii, f2fma(QaI, orr, f2fma(PbR, pim, f2mul(QbI, pr))));
            }
        }

        // ---- wires 5..8: in-register pair-index butterflies ----
#pragma unroll
        for (int w = 5; w <= 8; w++){
            const float c0=__shfl_sync(FULL,m0,w), c1=__shfl_sync(FULL,m1,w);
            const float c2=__shfl_sync(FULL,m2,w), c3=__shfl_sync(FULL,m3,w);
            const float c4=__shfl_sync(FULL,m4,w), c5=__shfl_sync(FULL,m5,w);
            const float c6=__shfl_sync(FULL,m6,w), c7=__shfl_sync(FULL,m7,w);
            const u64 Pr00=dup2(c0), Ni00=dup2(-c1), Qi00=dup2(c1);
            const u64 Pr01=dup2(c2), Ni01=dup2(-c3), Qi01=dup2(c3);
            const u64 Pr10=dup2(c4), Ni10=dup2(-c5), Qi10=dup2(c5);
            const u64 Pr11=dup2(c6), Ni11=dup2(-c7), Qi11=dup2(c7);
            const int SBc = 8 - w;               // pair-index bit
#pragma unroll
            for (int kk = 0; kk < 8; kk++){
                const int k0 = ((kk >> SBc) << (SBc + 1)) | (kk & ((1 << SBc) - 1));
                const int k1 = k0 | (1 << SBc);
                u64 a0r = vr[k0], a0i = vi[k0], a1r = vr[k1], a1i = vi[k1];
                vr[k0] = f2fma(Pr00, a0r, f2fma(Ni00, a0i, f2fma(Pr01, a1r, f2mul(Ni01, a1i))));
                vi[k0] = f2fma(Pr00, a0i, f2fma(Qi00, a0r, f2fma(Pr01, a1i, f2mul(Qi01, a1r))));
                vr[k1] = f2fma(Pr10, a0r, f2fma(Ni10, a0i, f2fma(Pr11, a1r, f2mul(Ni11, a1i))));
                vi[k1] = f2fma(Pr10, a0i, f2fma(Qi10, a0r, f2fma(Pr11, a1i, f2mul(Qi11, a1r))));
            }
        }

        // ---- wire 9: within-u64 butterfly ----
        {
            const float c0=__shfl_sync(FULL,m0,9), c1=__shfl_sync(FULL,m1,9);
            const float c2=__shfl_sync(FULL,m2,9), c3=__shfl_sync(FULL,m3,9);
            const float c4=__shfl_sync(FULL,m4,9), c5=__shfl_sync(FULL,m5,9);
            const float c6=__shfl_sync(FULL,m6,9), c7=__shfl_sync(FULL,m7,9);
            const u64 P1 = pk2(c0, c6),  P2 = pk2(c2, c4);
            const u64 N1 = pk2(-c1, -c7), N2 = pk2(-c3, -c5);
            const u64 Q1 = pk2(c1, c7),  Q2 = pk2(c3, c5);
#pragma unroll
            for (int k = 0; k < 16; k++){
                u64 xr = vr[k], xi_ = vi[k];
                u64 xsr = swp(xr), xsi = swp(xi_);
                vr[k] = f2fma(P1, xr,  f2fma(P2, xsr, f2fma(N1, xi_, f2mul(N2, xsi))));
                vi[k] = f2fma(P1, xi_, f2fma(P2, xsi, f2fma(Q1, xr,  f2mul(Q2, xsr))));
            }
        }

        // ---- CNOT-ring permutation (rounds 0..3) via smem, XOR-linear ----
        if (r < 4){
            __syncwarp();
            u64 tr[16];
#pragma unroll
            for (int k = 0; k < 16; k++) *(u64*)&buf[l * 34 + 2 * k] = vr[k];
            __syncwarp();
#pragma unroll
            for (int k = 0; k < 16; k++){
                const int j0 = 2 * k, j1 = 2 * k + 1;
                const int zj0 = ((j0&1)?B1:0) ^ ((j0&2)?B2:0) ^ ((j0&4)?B4:0) ^ ((j0&8)?B8:0) ^ ((j0&16)?B16:0);
                const int zj1 = zj0 ^ B1;        // j1 = j0 ^ 1
                const int z0 = zl ^ zj0, z1 = zl ^ zj1;
                tr[k] = pk2(buf[(z0 >> 5) * 34 + (z0 & 31)],
                            buf[(z1 >> 5) * 34 + (z1 & 31)]);
            }
            __syncwarp();
#pragma unroll
            for (int k = 0; k < 16; k++) *(u64*)&buf[l * 34 + 2 * k] = vi[k];
            __syncwarp();
#pragma unroll
            for (int k = 0; k < 16; k++){
                const int j0 = 2 * k, j1 = 2 * k + 1;
                const int zj0 = ((j0&1)?B1:0) ^ ((j0&2)?B2:0) ^ ((j0&4)?B4:0) ^ ((j0&8)?B8:0) ^ ((j0&16)?B16:0);
                const int zj1 = zj0 ^ B1;
                const int z0 = zl ^ zj0, z1 = zl ^ zj1;
                vi[k] = pk2(buf[(z0 >> 5) * 34 + (z0 & 31)],
                            buf[(z1 >> 5) * 34 + (z1 & 31)]);
                vr[k] = tr[k];
            }
            __syncwarp();
        }
    }

    // ---- probabilities: packed square-sum, transpose, bf16 hi/lo store ----
    __syncwarp();
#pragma unroll
    for (int k = 0; k < 16; k++)
        *(u64*)&buf[l * 34 + 2 * k] = f2fma(vr[k], vr[k], f2mul(vi[k], vi[k]));
    __syncwarp();
    const size_t o = (size_t)b * GQ + (size_t)g * QD;
#pragma unroll
    for (int j = 0; j < 32; j++){
        float p = buf[j * 34 + l];
        __nv_bfloat16 h = __float2bfloat16(p);
        ph[o + j * 32 + l] = h;
        pl[o + j * 32 + l] = __float2bfloat16(p - __bfloat162float(h));
    }
}

// ---------------- launch ----------------
extern "C" void kernel_launch(void* const* d_in, const int* in_sizes, int n_in,
                              void* d_out, int out_size)
{
    const float* x          = (const float*)d_in[0];
    const float* inp_scale  = (const float*)d_in[1];
    const float* proj_in_w  = (const float*)d_in[2];
    const float* proj_in_b  = (const float*)d_in[3];
    const float* reup_w     = (const float*)d_in[4];
    const float* reup_b     = (const float*)d_in[5];
    const float* q_weights  = (const float*)d_in[6];
    const float* upload_sc  = (const float*)d_in[7];
    const float* meas_w     = (const float*)d_in[8];
    const float* proj_out_w = (const float*)d_in[9];
    const float* proj_out_b = (const float*)d_in[10];
    float* out = (float*)d_out;

    void *pxq, *pang, *pph, *ppl, *pxh, *pxl, *pwih, *pwil, *pwoh, *pwol;
    cudaGetSymbolAddress(&pxq,  g_xq);
    cudaGetSymbolAddress(&pang, g_ang);
    cudaGetSymbolAddress(&pph,  g_ph);
    cudaGetSymbolAddress(&ppl,  g_pl);
    cudaGetSymbolAddress(&pxh,  g_xh);
    cudaGetSymbolAddress(&pxl,  g_xl);
    cudaGetSymbolAddress(&pwih, g_wih);
    cudaGetSymbolAddress(&pwil, g_wil);
    cudaGetSymbolAddress(&pwoh, g_woh);
    cudaGetSymbolAddress(&pwol, g_wol);

    // dynamic SMEM: BK=64. BN=128 -> 2*73728=147456; BN=64 -> 2*55296=110592
    cudaFuncSetAttribute(mma_gemm<128>, cudaFuncAttributeMaxDynamicSharedMemorySize, 147456);
    cudaFuncSetAttribute(mma_gemm<64>,  cudaFuncAttributeMaxDynamicSharedMemorySize, 110592);

    // ---- side streams + events (created once, on the uncaptured correctness
    // call; captured calls perform identical launches/edges every time).
    // Same 2-stream footprint that passed in R10; one extra event for angles.
    static cudaStream_t s1 = nullptr, s2 = nullptr;
    static cudaEvent_t ev_fork = nullptr, ev_wi = nullptr, ev_wo = nullptr, ev_ang = nullptr;
    if (!ev_fork){
        if (cudaStreamCreateWithFlags(&s1, cudaStreamNonBlocking) != cudaSuccess) s1 = nullptr;
        if (cudaStreamCreateWithFlags(&s2, cudaStreamNonBlocking) != cudaSuccess) s2 = nullptr;
        cudaEventCreateWithFlags(&ev_fork, cudaEventDisableTiming);
        cudaEventCreateWithFlags(&ev_wi,   cudaEventDisableTiming);
        cudaEventCreateWithFlags(&ev_wo,   cudaEventDisableTiming);
        cudaEventCreateWithFlags(&ev_ang,  cudaEventDisableTiming);
    }
    const cudaStream_t S1 = s1 ? s1 : (cudaStream_t)0;
    const cudaStream_t S2 = s2 ? s2 : (cudaStream_t)0;

    // fork: side streams start from here
    cudaEventRecord(ev_fork, 0);
    cudaStreamWaitEvent(S1, ev_fork, 0);
    cudaStreamWaitEvent(S2, ev_fork, 0);

    // S1: wi-split (gates GEMM-in)
    split_bf16v<<<(GQ*INd/4 + 255)/256, 256, 0, S1>>>((const float4*)proj_in_w, nullptr,
        (__nv_bfloat162*)pwih, (__nv_bfloat162*)pwil, GQ*INd/4);
    cudaEventRecord(ev_wi, S1);

    // S2: wo-split (gates GEMM-out), then angles (gates quantum) — both finish
    // well before their consumers need them.
    split_bf16v<<<(OUTd*GQ/4 + 255)/256, 256, 0, S2>>>((const float4*)proj_out_w, nullptr,
        (__nv_bfloat162*)pwoh, (__nv_bfloat162*)pwol, OUTd*GQ/4);
    cudaEventRecord(ev_wo, S2);
    angles_kernel<<<Bsz, 320, 0, S2>>>(x, inp_scale, reup_w, reup_b, (float*)pang);
    cudaEventRecord(ev_ang, S2);

    // main chain: x-split
    split_bf16v<<<(Bsz*INd/4 + 255)/256, 256>>>((const float4*)x, inp_scale,
        (__nv_bfloat162*)pxh, (__nv_bfloat162*)pxl, Bsz*INd/4);

    // join wi -> GEMM-in
    cudaStreamWaitEvent((cudaStream_t)0, ev_wi, 0);
    {
        dim3 grid(GQ/128, Bsz/128);
        mma_gemm<128><<<grid, 256, 147456>>>(Bsz, GQ, INd,
            (const __nv_bfloat16*)pxh, (const __nv_bfloat16*)pxl,
            (const __nv_bfloat16*)pwih, (const __nv_bfloat16*)pwil,
            proj_in_b, (float*)pxq);
    }

    // join angles -> quantum circuit
    cudaStreamWaitEvent((cudaStream_t)0, ev_ang, 0);
    quantum_pk<<<1024, 128>>>((const float*)pxq, (const float*)pang,
        q_weights, upload_sc, meas_w,
        (__nv_bfloat16*)pph, (__nv_bfloat16*)ppl);

    // join wo -> GEMM-out
    cudaStreamWaitEvent((cudaStream_t)0, ev_wo, 0);
    {
        dim3 grid(OUTd/64, Bsz/128);
        mma_gemm<64><<<grid, 256, 110592>>>(Bsz, OUTd, GQ,
            (const __nv_bfloat16*)pph, (const __nv_bfloat16*)ppl,
            (const __nv_bfloat16*)pwoh, (const __nv_bfloat16*)pwol,
            proj_out_b, out);
    }
}

// round 13
// speedup vs baseline: 1.1344x; 1.1022x over previous
#include <cuda_runtime.h>
#include <cuda_bf16.h>
#include <math.h>
#include <cstdint>

#define Bsz  1024
#define INd  1024
#define OUTd 1024
#define NQw  10
#define Gg   4
#define DPT  4
#define QD   1024
#define GQ   4096   // G * QDIM

typedef unsigned long long u64;

// ---------------- scratch (device globals: no allocation allowed) ----------
__device__ float g_xq[Bsz * GQ];        // 16 MB (GEMM-in output, fp32)
__device__ float g_probs[Bsz * GQ];     // 16 MB (quantum output, tf32-rounded)
__device__ float g_ang[Bsz * Gg * NQw]; // 160 KB
__device__ float g_xs[Bsz * INd];       // 4 MB  (x*scale, tf32-rounded)
__device__ float g_wi[GQ * INd];        // 16 MB (proj_in_w, tf32-rounded)
__device__ float g_wo[OUTd * GQ];       // 16 MB (proj_out_w, tf32-rounded)

// ================= small PTX helpers (family-stable only; NO tcgen05) ======
__device__ __forceinline__ uint32_t smem_u32(const void* p){
    uint32_t a;
    asm("{ .reg .u64 t; cvta.to.shared.u64 t, %1; cvt.u32.u64 %0, t; }" : "=r"(a) : "l"(p));
    return a;
}
__device__ __forceinline__ void cp16(uint32_t s, const void* g){
    asm volatile("cp.async.cg.shared.global [%0], [%1], 16;" :: "r"(s), "l"(g) : "memory");
}
__device__ __forceinline__ uint32_t lds32(uint32_t a){
    uint32_t v;
    asm volatile("ld.shared.b32 %0, [%1];" : "=r"(v) : "r"(a));
    return v;
}
__device__ __forceinline__ float rna_tf32(float x){
    uint32_t t;
    asm("cvt.rna.tf32.f32 %0, %1;" : "=r"(t) : "f"(x));
    return __uint_as_float(t);
}
__device__ __forceinline__ void mma_tf32(float* c, const uint32_t* a, const uint32_t* b){
    asm volatile(
        "mma.sync.aligned.m16n8k8.row.col.f32.tf32.tf32.f32 "
        "{%0,%1,%2,%3}, {%4,%5,%6,%7}, {%8,%9}, {%0,%1,%2,%3};"
        : "+f"(c[0]), "+f"(c[1]), "+f"(c[2]), "+f"(c[3])
        : "r"(a[0]), "r"(a[1]), "r"(a[2]), "r"(a[3]), "r"(b[0]), "r"(b[1]));
}

// ---- packed f32x2 (PTX ISA 8.6, sm_100+ family-generic) ----
__device__ __forceinline__ u64 f2fma(u64 a, u64 b, u64 c){
    u64 d; asm("fma.rn.f32x2 %0, %1, %2, %3;" : "=l"(d) : "l"(a), "l"(b), "l"(c)); return d;
}
__device__ __forceinline__ u64 f2mul(u64 a, u64 b){
    u64 d; asm("mul.rn.f32x2 %0, %1, %2;" : "=l"(d) : "l"(a), "l"(b)); return d;
}
__device__ __forceinline__ u64 pk2(float lo, float hi){
    u64 r;
    asm("mov.b64 %0, {%1, %2};" : "=l"(r) : "r"(__float_as_uint(lo)), "r"(__float_as_uint(hi)));
    return r;
}
__device__ __forceinline__ u64 dup2(float x){ return pk2(x, x); }
__device__ __forceinline__ void unpk(u64 v, float& a, float& b){
    uint32_t x, y;
    asm("mov.b64 {%0, %1}, %2;" : "=r"(x), "=r"(y) : "l"(v));
    a = __uint_as_float(x); b = __uint_as_float(y);
}
__device__ __forceinline__ u64 swp(u64 v){ float a, b; unpk(v, a, b); return pk2(b, a); }

// ================= tf32 rounding pass (optionally scaled), float4 ==========
__global__ void __launch_bounds__(256)
round_tf32v(const float4* __restrict__ src, const float* __restrict__ scale,
            float4* __restrict__ dst, int n4)
{
    int i = blockIdx.x * 256 + threadIdx.x;
    if (i < n4){
        float4 v = src[i];
        if (scale){
            int k = (4 * i) & (INd - 1);
            v.x *= scale[k]; v.y *= scale[k + 1]; v.z *= scale[k + 2]; v.w *= scale[k + 3];
        }
        v.x = rna_tf32(v.x); v.y = rna_tf32(v.y);
        v.z = rna_tf32(v.z); v.w = rna_tf32(v.w);
        dst[i] = v;
    }
}

// ================= TF32 GEMM: C[M,N] = A[M,K] @ B[N,K]^T + bias ============
// Operands pre-rounded to tf32 (cvt.rna); fp32 accum.
// CTA tile 128 x BN, BK=64, 8 warps (4m x 2n), warp tile 32 x (BN/2).
// 2-stage double buffer; prefetch after compute.
// SMEM rows: 64 fp32 + 4 pad = 272B -> bank (4*grp+tig)%32, conflict-free.
template<int BN>
__global__ void __launch_bounds__(256)
tf32_gemm(int M, int N, int K,
          const float* __restrict__ A, const float* __restrict__ B,
          const float* __restrict__ bias, float* __restrict__ C)
{
    constexpr int RS   = 272;             // bytes per row (68 floats)
    constexpr int A_BY = 128 * RS;
    constexpr int B_BY = BN * RS;
    constexpr int STG_ = A_BY + B_BY;
    constexpr int NT   = BN / 16;         // n8 tiles per warp
    extern __shared__ char smc[];

    const int tid  = threadIdx.x;
    const int wid  = tid >> 5, lane = tid & 31;
    const int grp  = lane >> 2, tig = lane & 3;
    const int wm   = wid & 3,  wn = wid >> 2;       // 4 x 2 warp grid
    const int m0   = blockIdx.y * 128, n0 = blockIdx.x * BN;
    const uint32_t sb = smem_u32(smc);

    float c[2][NT][4];
#pragma unroll
    for (int mt = 0; mt < 2; mt++)
#pragma unroll
        for (int nt = 0; nt < NT; nt++)
#pragma unroll
            for (int q = 0; q < 4; q++) c[mt][nt][q] = 0.f;

    const int nk = K >> 6;                // K chunks of 64

    auto do_prefetch = [&](int i){
        const int st = i & 1;
        const int k0 = i << 6;
        const uint32_t ba = sb + st * STG_;
#pragma unroll
        for (int v = tid; v < 2048; v += 256){     // A: 128 rows x 16 x 16B
            int r = v >> 4, ch = v & 15;
            cp16(ba + r * RS + ch * 16, A + (size_t)(m0 + r) * K + k0 + ch * 4);
        }
#pragma unroll
        for (int v = tid; v < BN * 16; v += 256){  // B: BN rows x 16 x 16B
            int r = v >> 4, ch = v & 15;
            cp16(ba + A_BY + r * RS + ch * 16, B + (size_t)(n0 + r) * K + k0 + ch * 4);
        }
        asm volatile("cp.async.commit_group;" ::: "memory");
    };

    do_prefetch(0);
    do_prefetch(1);

    for (int i = 0; i < nk; i++){
        if (i + 2 <= nk) asm volatile("cp.async.wait_group 1;" ::: "memory");
        else             asm volatile("cp.async.wait_group 0;" ::: "memory");
        __syncthreads();

        const uint32_t ba = sb + (i & 1) * STG_;
        const uint32_t bb = ba + A_BY;

#pragma unroll
        for (int kk = 0; kk < 8; kk++){
            uint32_t a[2][4];
#pragma unroll
            for (int mt = 0; mt < 2; mt++){
                const uint32_t oa = ba + (wm * 32 + mt * 16 + grp) * RS + (kk * 8 + tig) * 4;
                a[mt][0] = lds32(oa);
                a[mt][1] = lds32(oa + 8 * RS);
                a[mt][2] = lds32(oa + 16);
                a[mt][3] = lds32(oa + 8 * RS + 16);
            }
            uint32_t b[NT][2];
#pragma unroll
            for (int nt = 0; nt < NT; nt++){
                const uint32_t ob = bb + (wn * (NT * 8) + nt * 8 + grp) * RS + (kk * 8 + tig) * 4;
                b[nt][0] = lds32(ob);
                b[nt][1] = lds32(ob + 16);
            }
#pragma unroll
            for (int mt = 0; mt < 2; mt++)
#pragma unroll
                for (int nt = 0; nt < NT; nt++)
                    mma_tf32(c[mt][nt], a[mt], b[nt]);
        }
        __syncthreads();
        if (i + 2 < nk) do_prefetch(i + 2);
    }

    // epilogue (same C fragment layout as k16)
#pragma unroll
    for (int mt = 0; mt < 2; mt++){
        const int row0 = m0 + wm * 32 + mt * 16 + grp;
#pragma unroll
        for (int nt = 0; nt < NT; nt++){
            const int col = n0 + wn * (NT * 8) + nt * 8 + 2 * tig;
            const float b0 = bias[col], b1 = bias[col + 1];
            float2 v0 = make_float2(c[mt][nt][0] + b0, c[mt][nt][1] + b1);
            float2 v1 = make_float2(c[mt][nt][2] + b0, c[mt][nt][3] + b1);
            *(float2*)&C[(size_t)row0       * N + col] = v0;
            *(float2*)&C[(size_t)(row0 + 8) * N + col] = v1;
        }
    }
}

// ---------------- angles: ang[b, j] = tanh((x*s) . reup_w[j] + reup_b[j]) * pi
__global__ void __launch_bounds__(320)
angles_kernel(const float* __restrict__ x, const float* __restrict__ inp_scale,
              const float* __restrict__ reup_w, const float* __restrict__ reup_b,
              float* __restrict__ ang)
{
    __shared__ float xs[INd];
    int b = blockIdx.x;
    for (int k = threadIdx.x; k < INd; k += blockDim.x)
        xs[k] = x[(size_t)b * INd + k] * inp_scale[k];
    __syncthreads();
    int warp = threadIdx.x >> 5, lane = threadIdx.x & 31;
#pragma unroll
    for (int q = 0; q < 4; q++){
        int j = warp * 4 + q;            // j in [0,40)
        const float* w = reup_w + (size_t)j * INd;
        float acc = 0.f;
        for (int k = lane; k < INd; k += 32) acc = fmaf(xs[k], w[k], acc);
#pragma unroll
        for (int o = 16; o; o >>= 1) acc += __shfl_xor_sync(0xffffffffu, acc, o);
        if (lane == 0)
            ang[(size_t)b * (Gg * NQw) + j] = tanhf(acc + reup_b[j]) * 3.14159265358979323846f;
    }
}

// ---------------- complex 2x2 helpers ----------------
struct C2 { float re, im; };
__device__ __forceinline__ C2 cmul(C2 a, C2 b){ return {a.re*b.re - a.im*b.im, a.re*b.im + a.im*b.re}; }
__device__ __forceinline__ C2 cadd(C2 a, C2 b){ return {a.re+b.re, a.im+b.im}; }
struct M2 { C2 m00, m01, m10, m11; };
__device__ __forceinline__ M2 mmul(M2 A, M2 B){  // A @ B
    M2 r;
    r.m00 = cadd(cmul(A.m00,B.m00), cmul(A.m01,B.m10));
    r.m01 = cadd(cmul(A.m00,B.m01), cmul(A.m01,B.m11));
    r.m10 = cadd(cmul(A.m10,B.m00), cmul(A.m11,B.m10));
    r.m11 = cadd(cmul(A.m10,B.m01), cmul(A.m11,B.m11));
    return r;
}
__device__ __forceinline__ M2 ry_m(float t){
    float c=cosf(0.5f*t), s=sinf(0.5f*t);
    return {{c,0.f},{-s,0.f},{s,0.f},{c,0.f}};
}
__device__ __forceinline__ M2 rx_m(float t){
    float c=cosf(0.5f*t), s=sinf(0.5f*t);
    return {{c,0.f},{0.f,-s},{0.f,-s},{c,0.f}};
}
__device__ __forceinline__ M2 u3_m(float t,float p,float l){
    float c=cosf(0.5f*t), s=sinf(0.5f*t);
    float cp=cosf(p), sp=sinf(p), cl=cosf(l), sl=sinf(l);
    M2 r;
    r.m00 = {c, 0.f};
    r.m01 = {-cl*s, -sl*s};
    r.m10 = {cp*s, sp*s};
    r.m11 = {(cp*cl - sp*sl)*c, (sp*cl + cp*sl)*c};
    return r;
}

// CNOT-ring permutation is XOR-linear: perm(a^b) = perm(a)^perm(b)
__device__ __forceinline__ int permL(int y){
#pragma unroll
    for (int k = 9; k >= 0; --k){
        int cb  = 9 - k;
        int tb2 = 9 - ((k + 1) % 10);
        y ^= ((y >> cb) & 1) << tb2;
    }
    return y;
}

// ================= quantum circuit: one WARP per (b,g) state ===============
// Lane l holds amps l*32+j (j=0..31), packed 2 amps per u64 over amp bit 0.
// Wires 0-4: lane-bit butterflies (shfl_xor). Wires 5-8: in-register.
// Wire 9: within-u64 butterfly. Output: probs fp32 (tf32-rounded for GEMM-out).
__global__ void __launch_bounds__(128)
quantum_pk(const float* __restrict__ xq, const float* __restrict__ ang,
           const float* __restrict__ qw, const float* __restrict__ us,
           const float* __restrict__ mw, float* __restrict__ probs)
{
    __shared__ __align__(16) float ss[4][34 * 32];   // per-warp bounce (stride 34)
    const int wid = threadIdx.x >> 5, l = threadIdx.x & 31;
    const int s = blockIdx.x * 4 + wid;
    const int b = s >> 2, g = s & 3;
    const unsigned FULL = 0xffffffffu;
    float* buf = ss[wid];

    // permutation basis (constants per lane)
    const int zl  = permL(l << 5);
    const int B1  = permL(1), B2 = permL(2), B4 = permL(4), B8 = permL(8), B16 = permL(16);

    // ---- load (coalesced) -> transpose via smem -> packed registers ----
    const float* xrow = xq + (size_t)b * GQ + (size_t)g * QD;
#pragma unroll
    for (int j = 0; j < 32; j++) buf[j * 34 + l] = xrow[j * 32 + l];
    __syncwarp();
    u64 vr[16], vi[16];
    u64 acc2 = 0ull;
#pragma unroll
    for (int k = 0; k < 16; k++){
        vr[k] = *(const u64*)&buf[l * 34 + 2 * k];
        acc2  = f2fma(vr[k], vr[k], acc2);
        vi[k] = 0ull;
    }
    float na, nb; unpk(acc2, na, nb);
    float nrm = na + nb;
#pragma unroll
    for (int o = 16; o; o >>= 1) nrm += __shfl_xor_sync(FULL, nrm, o);
    const u64 iv = dup2(1.0f / (sqrtf(nrm) + 1e-9f));
#pragma unroll
    for (int k = 0; k < 16; k++) vr[k] = f2mul(iv, vr[k]);
    __syncwarp();

    for (int r = 0; r < 5; r++){
        // ---- lanes 0..9 build fused 2x2 gate matrix for wire l ----
        float m0=0,m1=0,m2=0,m3=0,m4=0,m5=0,m6=0,m7=0;
        if (l < NQw){
            const int i = l;
            M2 M;
            if (r < 4){
                float a = ang[(size_t)b * (Gg * NQw) + g * NQw + i];
                float theta = a * us[(g * DPT + r) * NQw + i];
                if (r > 0) theta += qw[((g * DPT + (r - 1)) * NQw + i) * 3 + 2];
                const float* q = qw + ((size_t)(g * DPT + r) * NQw + i) * 3;
                M = mmul(ry_m(q[1]), mmul(rx_m(q[0]), ry_m(theta)));
            } else {
                const float* m = mw + ((size_t)g * NQw + i) * 3;
                float t2 = qw[((g * DPT + 3) * NQw + i) * 3 + 2];
                M = mmul(u3_m(m[0], m[1], m[2]), ry_m(t2));
            }
            m0=M.m00.re; m1=M.m00.im; m2=M.m01.re; m3=M.m01.im;
            m4=M.m10.re; m5=M.m10.im; m6=M.m11.re; m7=M.m11.im;
        }

        // ---- wires 0..4: lane-bit butterflies ----
#pragma unroll
        for (int i = 0; i < 5; i++){
            const float c0=__shfl_sync(FULL,m0,i), c1=__shfl_sync(FULL,m1,i);
            const float c2=__shfl_sync(FULL,m2,i), c3=__shfl_sync(FULL,m3,i);
            const float c4=__shfl_sync(FULL,m4,i), c5=__shfl_sync(FULL,m5,i);
            const float c6=__shfl_sync(FULL,m6,i), c7=__shfl_sync(FULL,m7,i);
            const int lb = 4 - i, msk = 1 << lb;
            const bool hb = (l >> lb) & 1;
            const float aR = hb ? c6 : c0, aI = hb ? c7 : c1;   // m11 : m00
            const float bR = hb ? c4 : c2, bI = hb ? c5 : c3;   // m10 : m01
            const u64 PaR = dup2(aR), NaI = dup2(-aI), QaI = dup2(aI);
            const u64 PbR = dup2(bR), NbI = dup2(-bI), QbI = dup2(bI);
#pragma unroll
            for (int k = 0; k < 16; k++){
                u64 pr  = __shfl_xor_sync(FULL, vr[k], msk);
                u64 pim = __shfl_xor_sync(FULL, vi[k], msk);
                u64 orr = vr[k], oii = vi[k];
                vr[k] = f2fma(PaR, orr, f2fma(NaI, oii, f2fma(PbR, pr,  f2mul(NbI, pim))));
                vi[k] = f2fma(PaR, oii, f2fma(QaI, orr, f2fma(PbR, pim, f2mul(QbI, pr))));
            }
        }

        // ---- wires 5..8: in-register pair-index butterflies ----
#pragma unroll
        for (int w = 5; w <= 8; w++){
            const float c0=__shfl_sync(FULL,m0,w), c1=__shfl_sync(FULL,m1,w);
            const float c2=__shfl_sync(FULL,m2,w), c3=__shfl_sync(FULL,m3,w);
            const float c4=__shfl_sync(FULL,m4,w), c5=__shfl_sync(FULL,m5,w);
            const float c6=__shfl_sync(FULL,m6,w), c7=__shfl_sync(FULL,m7,w);
            const u64 Pr00=dup2(c0), Ni00=dup2(-c1), Qi00=dup2(c1);
            const u64 Pr01=dup2(c2), Ni01=dup2(-c3), Qi01=dup2(c3);
            const u64 Pr10=dup2(c4), Ni10=dup2(-c5), Qi10=dup2(c5);
            const u64 Pr11=dup2(c6), Ni11=dup2(-c7), Qi11=dup2(c7);
            const int SBc = 8 - w;               // pair-index bit
#pragma unroll
            for (int kk = 0; kk < 8; kk++){
                const int k0 = ((kk >> SBc) << (SBc + 1)) | (kk & ((1 << SBc) - 1));
                const int k1 = k0 | (1 << SBc);
                u64 a0r = vr[k0], a0i = vi[k0], a1r = vr[k1], a1i = vi[k1];
                vr[k0] = f2fma(Pr00, a0r, f2fma(Ni00, a0i, f2fma(Pr01, a1r, f2mul(Ni01, a1i))));
                vi[k0] = f2fma(Pr00, a0i, f2fma(Qi00, a0r, f2fma(Pr01, a1i, f2mul(Qi01, a1r))));
                vr[k1] = f2fma(Pr10, a0r, f2fma(Ni10, a0i, f2fma(Pr11, a1r, f2mul(Ni11, a1i))));
                vi[k1] = f2fma(Pr10, a0i, f2fma(Qi10, a0r, f2fma(Pr11, a1i, f2mul(Qi11, a1r))));
            }
        }

        // ---- wire 9: within-u64 butterfly ----
        {
            const float c0=__shfl_sync(FULL,m0,9), c1=__shfl_sync(FULL,m1,9);
            const float c2=__shfl_sync(FULL,m2,9), c3=__shfl_sync(FULL,m3,9);
            const float c4=__shfl_sync(FULL,m4,9), c5=__shfl_sync(FULL,m5,9);
            const float c6=__shfl_sync(FULL,m6,9), c7=__shfl_sync(FULL,m7,9);
            const u64 P1 = pk2(c0, c6),  P2 = pk2(c2, c4);
            const u64 N1 = pk2(-c1, -c7), N2 = pk2(-c3, -c5);
            const u64 Q1 = pk2(c1, c7),  Q2 = pk2(c3, c5);
#pragma unroll
            for (int k = 0; k < 16; k++){
                u64 xr = vr[k], xi_ = vi[k];
                u64 xsr = swp(xr), xsi = swp(xi_);
                vr[k] = f2fma(P1, xr,  f2fma(P2, xsr, f2fma(N1, xi_, f2mul(N2, xsi))));
                vi[k] = f2fma(P1, xi_, f2fma(P2, xsi, f2fma(Q1, xr,  f2mul(Q2, xsr))));
            }
        }

        // ---- CNOT-ring permutation (rounds 0..3) via smem, XOR-linear ----
        if (r < 4){
            __syncwarp();
            u64 tr[16];
#pragma unroll
            for (int k = 0; k < 16; k++) *(u64*)&buf[l * 34 + 2 * k] = vr[k];
            __syncwarp();
#pragma unroll
            for (int k = 0; k < 16; k++){
                const int j0 = 2 * k, j1 = 2 * k + 1;
                const int zj0 = ((j0&1)?B1:0) ^ ((j0&2)?B2:0) ^ ((j0&4)?B4:0) ^ ((j0&8)?B8:0) ^ ((j0&16)?B16:0);
                const int zj1 = zj0 ^ B1;        // j1 = j0 ^ 1
                const int z0 = zl ^ zj0, z1 = zl ^ zj1;
                tr[k] = pk2(buf[(z0 >> 5) * 34 + (z0 & 31)],
                            buf[(z1 >> 5) * 34 + (z1 & 31)]);
            }
            __syncwarp();
#pragma unroll
            for (int k = 0; k < 16; k++) *(u64*)&buf[l * 34 + 2 * k] = vi[k];
            __syncwarp();
#pragma unroll
            for (int k = 0; k < 16; k++){
                const int j0 = 2 * k, j1 = 2 * k + 1;
                const int zj0 = ((j0&1)?B1:0) ^ ((j0&2)?B2:0) ^ ((j0&4)?B4:0) ^ ((j0&8)?B8:0) ^ ((j0&16)?B16:0);
                const int zj1 = zj0 ^ B1;
                const int z0 = zl ^ zj0, z1 = zl ^ zj1;
                vi[k] = pk2(buf[(z0 >> 5) * 34 + (z0 & 31)],
                            buf[(z1 >> 5) * 34 + (z1 & 31)]);
                vr[k] = tr[k];
            }
            __syncwarp();
        }
    }

    // ---- probabilities: packed square-sum, transpose, tf32-rounded store ----
    __syncwarp();
#pragma unroll
    for (int k = 0; k < 16; k++)
        *(u64*)&buf[l * 34 + 2 * k] = f2fma(vr[k], vr[k], f2mul(vi[k], vi[k]));
    __syncwarp();
    const size_t o = (size_t)b * GQ + (size_t)g * QD;
#pragma unroll
    for (int j = 0; j < 32; j++)
        probs[o + j * 32 + l] = rna_tf32(buf[j * 34 + l]);
}

// ---------------- launch ----------------
extern "C" void kernel_launch(void* const* d_in, const int* in_sizes, int n_in,
                              void* d_out, int out_size)
{
    const float* x          = (const float*)d_in[0];
    const float* inp_scale  = (const float*)d_in[1];
    const float* proj_in_w  = (const float*)d_in[2];
    const float* proj_in_b  = (const float*)d_in[3];
    const float* reup_w     = (const float*)d_in[4];
    const float* reup_b     = (const float*)d_in[5];
    const float* q_weights  = (const float*)d_in[6];
    const float* upload_sc  = (const float*)d_in[7];
    const float* meas_w     = (const float*)d_in[8];
    const float* proj_out_w = (const float*)d_in[9];
    const float* proj_out_b = (const float*)d_in[10];
    float* out = (float*)d_out;

    void *pxq, *pprobs, *pang, *pxs, *pwi, *pwo;
    cudaGetSymbolAddress(&pxq,    g_xq);
    cudaGetSymbolAddress(&pprobs, g_probs);
    cudaGetSymbolAddress(&pang,   g_ang);
    cudaGetSymbolAddress(&pxs,    g_xs);
    cudaGetSymbolAddress(&pwi,    g_wi);
    cudaGetSymbolAddress(&pwo,    g_wo);
    float* xq    = (float*)pxq;
    float* probs = (float*)pprobs;
    float* angp  = (float*)pang;
    float* xs    = (float*)pxs;
    float* wi    = (float*)pwi;
    float* wo    = (float*)pwo;

    // dynamic SMEM: BN=128 -> 2*(256*272)=139264; BN=64 -> 2*(192*272)=104448
    cudaFuncSetAttribute(tf32_gemm<128>, cudaFuncAttributeMaxDynamicSharedMemorySize, 139264);
    cudaFuncSetAttribute(tf32_gemm<64>,  cudaFuncAttributeMaxDynamicSharedMemorySize, 104448);

    // ---- side streams + events (created once, outside capture); same
    // footprint as the R12 passing config: 2 streams, 4 events. ----
    static cudaStream_t s1 = nullptr, s2 = nullptr;
    static cudaEvent_t ev_fork = nullptr, ev_wi = nullptr, ev_wo = nullptr, ev_ang = nullptr;
    if (!ev_fork){
        if (cudaStreamCreateWithFlags(&s1, cudaStreamNonBlocking) != cudaSuccess) s1 = nullptr;
        if (cudaStreamCreateWithFlags(&s2, cudaStreamNonBlocking) != cudaSuccess) s2 = nullptr;
        cudaEventCreateWithFlags(&ev_fork, cudaEventDisableTiming);
        cudaEventCreateWithFlags(&ev_wi,   cudaEventDisableTiming);
        cudaEventCreateWithFlags(&ev_wo,   cudaEventDisableTiming);
        cudaEventCreateWithFlags(&ev_ang,  cudaEventDisableTiming);
    }
    const cudaStream_t S1 = s1 ? s1 : (cudaStream_t)0;
    const cudaStream_t S2 = s2 ? s2 : (cudaStream_t)0;

    // fork: side streams start here
    cudaEventRecord(ev_fork, 0);
    cudaStreamWaitEvent(S1, ev_fork, 0);
    cudaStreamWaitEvent(S2, ev_fork, 0);

    // S1: round proj_in_w -> tf32 (gates GEMM-in)
    round_tf32v<<<(GQ*INd/4 + 255)/256, 256, 0, S1>>>((const float4*)proj_in_w, nullptr,
        (float4*)wi, GQ*INd/4);
    cudaEventRecord(ev_wi, S1);

    // S2: round proj_out_w -> tf32 (gates GEMM-out), then angles (gates quantum)
    round_tf32v<<<(OUTd*GQ/4 + 255)/256, 256, 0, S2>>>((const float4*)proj_out_w, nullptr,
        (float4*)wo, OUTd*GQ/4);
    cudaEventRecord(ev_wo, S2);
    angles_kernel<<<Bsz, 320, 0, S2>>>(x, inp_scale, reup_w, reup_b, angp);
    cudaEventRecord(ev_ang, S2);

    // main chain: x * scale -> tf32
    round_tf32v<<<(Bsz*INd/4 + 255)/256, 256>>>((const float4*)x, inp_scale,
        (float4*)xs, Bsz*INd/4);

    // join wi -> GEMM-in (tf32): xq[1024,4096] = xs @ wi^T + b
    cudaStreamWaitEvent((cudaStream_t)0, ev_wi, 0);
    {
        dim3 grid(GQ/128, Bsz/128);
        tf32_gemm<128><<<grid, 256, 139264>>>(Bsz, GQ, INd, xs, wi, proj_in_b, xq);
    }

    // join angles -> quantum circuit (4096 states, one warp each)
    cudaStreamWaitEvent((cudaStream_t)0, ev_ang, 0);
    quantum_pk<<<1024, 128>>>(xq, angp, q_weights, upload_sc, meas_w, probs);

    // join wo -> GEMM-out (tf32): out[1024,1024] = probs @ wo^T + b
    cudaStreamWaitEvent((cudaStream_t)0, ev_wo, 0);
    {
        dim3 grid(OUTd/64, Bsz/128);
        tf32_gemm<64><<<grid, 256, 104448>>>(Bsz, OUTd, GQ, probs, wo, proj_out_b, out);
    }
}

// round 14
// speedup vs baseline: 1.2907x; 1.1377x over previous
#include <cuda_runtime.h>
#include <cuda_bf16.h>
#include <math.h>
#include <cstdint>

#define Bsz  1024
#define INd  1024
#define OUTd 1024
#define NQw  10
#define Gg   4
#define DPT  4
#define QD   1024
#define GQ   4096   // G * QDIM

typedef unsigned long long u64;

// ---------------- scratch (device globals: no allocation allowed) ----------
__device__ float g_xq[Bsz * GQ];        // 16 MB (GEMM-in output, fp32)
__device__ float g_probs[Bsz * GQ];     // 16 MB (quantum output, tf32-rounded)
__device__ float g_ang[Bsz * Gg * NQw]; // 160 KB
__device__ float g_xs[Bsz * INd];       // 4 MB  (x*scale, tf32-rounded)
__device__ float g_wi[GQ * INd];        // 16 MB (proj_in_w, tf32-rounded)
__device__ float g_wo[OUTd * GQ];       // 16 MB (proj_out_w, tf32-rounded)
__device__ float g_part[4 * Bsz * OUTd];// 16 MB (gout split-K partials)

// ================= small PTX helpers (family-stable only; NO tcgen05) ======
__device__ __forceinline__ uint32_t smem_u32(const void* p){
    uint32_t a;
    asm("{ .reg .u64 t; cvta.to.shared.u64 t, %1; cvt.u32.u64 %0, t; }" : "=r"(a) : "l"(p));
    return a;
}
__device__ __forceinline__ void cp16(uint32_t s, const void* g){
    asm volatile("cp.async.cg.shared.global [%0], [%1], 16;" :: "r"(s), "l"(g) : "memory");
}
__device__ __forceinline__ uint32_t lds32(uint32_t a){
    uint32_t v;
    asm volatile("ld.shared.b32 %0, [%1];" : "=r"(v) : "r"(a));
    return v;
}
__device__ __forceinline__ float rna_tf32(float x){
    uint32_t t;
    asm("cvt.rna.tf32.f32 %0, %1;" : "=r"(t) : "f"(x));
    return __uint_as_float(t);
}
__device__ __forceinline__ void mma_tf32(float* c, const uint32_t* a, const uint32_t* b){
    asm volatile(
        "mma.sync.aligned.m16n8k8.row.col.f32.tf32.tf32.f32 "
        "{%0,%1,%2,%3}, {%4,%5,%6,%7}, {%8,%9}, {%0,%1,%2,%3};"
        : "+f"(c[0]), "+f"(c[1]), "+f"(c[2]), "+f"(c[3])
        : "r"(a[0]), "r"(a[1]), "r"(a[2]), "r"(a[3]), "r"(b[0]), "r"(b[1]));
}

// ---- packed f32x2 (PTX ISA 8.6, sm_100+ family-generic) ----
__device__ __forceinline__ u64 f2fma(u64 a, u64 b, u64 c){
    u64 d; asm("fma.rn.f32x2 %0, %1, %2, %3;" : "=l"(d) : "l"(a), "l"(b), "l"(c)); return d;
}
__device__ __forceinline__ u64 f2mul(u64 a, u64 b){
    u64 d; asm("mul.rn.f32x2 %0, %1, %2;" : "=l"(d) : "l"(a), "l"(b)); return d;
}
__device__ __forceinline__ u64 pk2(float lo, float hi){
    u64 r;
    asm("mov.b64 %0, {%1, %2};" : "=l"(r) : "r"(__float_as_uint(lo)), "r"(__float_as_uint(hi)));
    return r;
}
__device__ __forceinline__ u64 dup2(float x){ return pk2(x, x); }
__device__ __forceinline__ void unpk(u64 v, float& a, float& b){
    uint32_t x, y;
    asm("mov.b64 {%0, %1}, %2;" : "=r"(x), "=r"(y) : "l"(v));
    a = __uint_as_float(x); b = __uint_as_float(y);
}
__device__ __forceinline__ u64 swp(u64 v){ float a, b; unpk(v, a, b); return pk2(b, a); }

// ================= tf32 rounding pass (optionally scaled), float4 ==========
__global__ void __launch_bounds__(256)
round_tf32v(const float4* __restrict__ src, const float* __restrict__ scale,
            float4* __restrict__ dst, int n4)
{
    int i = blockIdx.x * 256 + threadIdx.x;
    if (i < n4){
        float4 v = src[i];
        if (scale){
            int k = (4 * i) & (INd - 1);
            v.x *= scale[k]; v.y *= scale[k + 1]; v.z *= scale[k + 2]; v.w *= scale[k + 3];
        }
        v.x = rna_tf32(v.x); v.y = rna_tf32(v.y);
        v.z = rna_tf32(v.z); v.w = rna_tf32(v.w);
        dst[i] = v;
    }
}

// ================= split-K reduce: out = sum_z part[z] + bias ==============
__global__ void __launch_bounds__(256)
reduce4(const float4* __restrict__ part, const float* __restrict__ bias,
        float4* __restrict__ out, int n4)
{
    int i = blockIdx.x * 256 + threadIdx.x;
    if (i < n4){
        float4 a = part[i];
        float4 b = part[i + n4];
        float4 c = part[i + 2 * n4];
        float4 d = part[i + 3 * n4];
        int cb = (4 * i) & (OUTd - 1);
        float4 r;
        r.x = a.x + b.x + c.x + d.x + bias[cb];
        r.y = a.y + b.y + c.y + d.y + bias[cb + 1];
        r.z = a.z + b.z + c.z + d.z + bias[cb + 2];
        r.w = a.w + b.w + c.w + d.w + bias[cb + 3];
        out[i] = r;
    }
}

// ================= TF32 GEMM: C[M,N] = A[M,K] @ B[N,K]^T (+ bias) ==========
// Operands pre-rounded to tf32 (cvt.rna); fp32 accum.
// CTA tile 256 x 128, BK=64, 8 warps (4m x 2n), warp tile 64 x 64.
// 128B smem fragment traffic per MMA -> LDS/tensor balanced.
// Split-K over blockIdx.z: each z handles K/gridDim.z, C += z*M*N, bias may
// be null (partials). SMEM rows: 68 floats (272B) -> conflict-free lds32.
__global__ void __launch_bounds__(256)
tf32_gemm(int M, int N, int K,
          const float* __restrict__ A, const float* __restrict__ B,
          const float* __restrict__ bias, float* __restrict__ C)
{
    constexpr int RS   = 272;             // bytes per row (68 floats)
    constexpr int A_BY = 256 * RS;        // 69632
    constexpr int B_BY = 128 * RS;        // 34816
    constexpr int STG_ = A_BY + B_BY;     // 104448
    extern __shared__ char smc[];

    const int tid  = threadIdx.x;
    const int wid  = tid >> 5, lane = tid & 31;
    const int grp  = lane >> 2, tig = lane & 3;
    const int wm   = wid & 3,  wn = wid >> 2;       // 4 x 2 warp grid
    const int m0   = blockIdx.y * 256, n0 = blockIdx.x * 128;
    const uint32_t sb = smem_u32(smc);

    const int Kz    = K / gridDim.z;                // K per split
    const int kbase = blockIdx.z * Kz;
    C += (size_t)blockIdx.z * M * N;

    float c[4][8][4];
#pragma unroll
    for (int mt = 0; mt < 4; mt++)
#pragma unroll
        for (int nt = 0; nt < 8; nt++)
#pragma unroll
            for (int q = 0; q < 4; q++) c[mt][nt][q] = 0.f;

    const int nk = Kz >> 6;               // K chunks of 64

    auto do_prefetch = [&](int i){
        const int st = i & 1;
        const int k0 = kbase + (i << 6);
        const uint32_t ba = sb + st * STG_;
#pragma unroll
        for (int v = tid; v < 4096; v += 256){     // A: 256 rows x 16 x 16B
            int r = v >> 4, ch = v & 15;
            cp16(ba + r * RS + ch * 16, A + (size_t)(m0 + r) * K + k0 + ch * 4);
        }
#pragma unroll
        for (int v = tid; v < 2048; v += 256){     // B: 128 rows x 16 x 16B
            int r = v >> 4, ch = v & 15;
            cp16(ba + A_BY + r * RS + ch * 16, B + (size_t)(n0 + r) * K + k0 + ch * 4);
        }
        asm volatile("cp.async.commit_group;" ::: "memory");
    };

    do_prefetch(0);
    do_prefetch(1);

    for (int i = 0; i < nk; i++){
        if (i + 2 <= nk) asm volatile("cp.async.wait_group 1;" ::: "memory");
        else             asm volatile("cp.async.wait_group 0;" ::: "memory");
        __syncthreads();

        const uint32_t ba = sb + (i & 1) * STG_;
        const uint32_t bb = ba + A_BY;

#pragma unroll
        for (int kk = 0; kk < 8; kk++){
            uint32_t a[4][4];
#pragma unroll
            for (int mt = 0; mt < 4; mt++){
                const uint32_t oa = ba + (wm * 64 + mt * 16 + grp) * RS + (kk * 8 + tig) * 4;
                a[mt][0] = lds32(oa);
                a[mt][1] = lds32(oa + 8 * RS);
                a[mt][2] = lds32(oa + 16);
                a[mt][3] = lds32(oa + 8 * RS + 16);
            }
            uint32_t b[8][2];
#pragma unroll
            for (int nt = 0; nt < 8; nt++){
                const uint32_t ob = bb + (wn * 64 + nt * 8 + grp) * RS + (kk * 8 + tig) * 4;
                b[nt][0] = lds32(ob);
                b[nt][1] = lds32(ob + 16);
            }
#pragma unroll
            for (int mt = 0; mt < 4; mt++)
#pragma unroll
                for (int nt = 0; nt < 8; nt++)
                    mma_tf32(c[mt][nt], a[mt], b[nt]);
        }
        __syncthreads();
        if (i + 2 < nk) do_prefetch(i + 2);
    }

    // epilogue
#pragma unroll
    for (int mt = 0; mt < 4; mt++){
        const int row0 = m0 + wm * 64 + mt * 16 + grp;
#pragma unroll
        for (int nt = 0; nt < 8; nt++){
            const int col = n0 + wn * 64 + nt * 8 + 2 * tig;
            float b0 = 0.f, b1 = 0.f;
            if (bias){ b0 = bias[col]; b1 = bias[col + 1]; }
            float2 v0 = make_float2(c[mt][nt][0] + b0, c[mt][nt][1] + b1);
            float2 v1 = make_float2(c[mt][nt][2] + b0, c[mt][nt][3] + b1);
            *(float2*)&C[(size_t)row0       * N + col] = v0;
            *(float2*)&C[(size_t)(row0 + 8) * N + col] = v1;
        }
    }
}

// ---------------- angles: ang[b, j] = tanh((x*s) . reup_w[j] + reup_b[j]) * pi
__global__ void __launch_bounds__(320)
angles_kernel(const float* __restrict__ x, const float* __restrict__ inp_scale,
              const float* __restrict__ reup_w, const float* __restrict__ reup_b,
              float* __restrict__ ang)
{
    __shared__ float xs[INd];
    int b = blockIdx.x;
    for (int k = threadIdx.x; k < INd; k += blockDim.x)
        xs[k] = x[(size_t)b * INd + k] * inp_scale[k];
    __syncthreads();
    int warp = threadIdx.x >> 5, lane = threadIdx.x & 31;
#pragma unroll
    for (int q = 0; q < 4; q++){
        int j = warp * 4 + q;            // j in [0,40)
        const float* w = reup_w + (size_t)j * INd;
        float acc = 0.f;
        for (int k = lane; k < INd; k += 32) acc = fmaf(xs[k], w[k], acc);
#pragma unroll
        for (int o = 16; o; o >>= 1) acc += __shfl_xor_sync(0xffffffffu, acc, o);
        if (lane == 0)
            ang[(size_t)b * (Gg * NQw) + j] = tanhf(acc + reup_b[j]) * 3.14159265358979323846f;
    }
}

// ---------------- complex 2x2 helpers ----------------
struct C2 { float re, im; };
__device__ __forceinline__ C2 cmul(C2 a, C2 b){ return {a.re*b.re - a.im*b.im, a.re*b.im + a.im*b.re}; }
__device__ __forceinline__ C2 cadd(C2 a, C2 b){ return {a.re+b.re, a.im+b.im}; }
struct M2 { C2 m00, m01, m10, m11; };
__device__ __forceinline__ M2 mmul(M2 A, M2 B){  // A @ B
    M2 r;
    r.m00 = cadd(cmul(A.m00,B.m00), cmul(A.m01,B.m10));
    r.m01 = cadd(cmul(A.m00,B.m01), cmul(A.m01,B.m11));
    r.m10 = cadd(cmul(A.m10,B.m00), cmul(A.m11,B.m10));
    r.m11 = cadd(cmul(A.m10,B.m01), cmul(A.m11,B.m11));
    return r;
}
__device__ __forceinline__ M2 ry_m(float t){
    float c=cosf(0.5f*t), s=sinf(0.5f*t);
    return {{c,0.f},{-s,0.f},{s,0.f},{c,0.f}};
}
__device__ __forceinline__ M2 rx_m(float t){
    float c=cosf(0.5f*t), s=sinf(0.5f*t);
    return {{c,0.f},{0.f,-s},{0.f,-s},{c,0.f}};
}
__device__ __forceinline__ M2 u3_m(float t,float p,float l){
    float c=cosf(0.5f*t), s=sinf(0.5f*t);
    float cp=cosf(p), sp=sinf(p), cl=cosf(l), sl=sinf(l);
    M2 r;
    r.m00 = {c, 0.f};
    r.m01 = {-cl*s, -sl*s};
    r.m10 = {cp*s, sp*s};
    r.m11 = {(cp*cl - sp*sl)*c, (sp*cl + cp*sl)*c};
    return r;
}

// CNOT-ring permutation is XOR-linear: perm(a^b) = perm(a)^perm(b)
__device__ __forceinline__ int permL(int y){
#pragma unroll
    for (int k = 9; k >= 0; --k){
        int cb  = 9 - k;
        int tb2 = 9 - ((k + 1) % 10);
        y ^= ((y >> cb) & 1) << tb2;
    }
    return y;
}

// ================= quantum circuit: one WARP per (b,g) state ===============
__global__ void __launch_bounds__(128)
quantum_pk(const float* __restrict__ xq, const float* __restrict__ ang,
           const float* __restrict__ qw, const float* __restrict__ us,
           const float* __restrict__ mw, float* __restrict__ probs)
{
    __shared__ __align__(16) float ss[4][34 * 32];   // per-warp bounce (stride 34)
    const int wid = threadIdx.x >> 5, l = threadIdx.x & 31;
    const int s = blockIdx.x * 4 + wid;
    const int b = s >> 2, g = s & 3;
    const unsigned FULL = 0xffffffffu;
    float* buf = ss[wid];

    const int zl  = permL(l << 5);
    const int B1  = permL(1), B2 = permL(2), B4 = permL(4), B8 = permL(8), B16 = permL(16);

    const float* xrow = xq + (size_t)b * GQ + (size_t)g * QD;
#pragma unroll
    for (int j = 0; j < 32; j++) buf[j * 34 + l] = xrow[j * 32 + l];
    __syncwarp();
    u64 vr[16], vi[16];
    u64 acc2 = 0ull;
#pragma unroll
    for (int k = 0; k < 16; k++){
        vr[k] = *(const u64*)&buf[l * 34 + 2 * k];
        acc2  = f2fma(vr[k], vr[k], acc2);
        vi[k] = 0ull;
    }
    float na, nb; unpk(acc2, na, nb);
    float nrm = na + nb;
#pragma unroll
    for (int o = 16; o; o >>= 1) nrm += __shfl_xor_sync(FULL, nrm, o);
    const u64 iv = dup2(1.0f / (sqrtf(nrm) + 1e-9f));
#pragma unroll
    for (int k = 0; k < 16; k++) vr[k] = f2mul(iv, vr[k]);
    __syncwarp();

    for (int r = 0; r < 5; r++){
        float m0=0,m1=0,m2=0,m3=0,m4=0,m5=0,m6=0,m7=0;
        if (l < NQw){
            const int i = l;
            M2 M;
            if (r < 4){
                float a = ang[(size_t)b * (Gg * NQw) + g * NQw + i];
                float theta = a * us[(g * DPT + r) * NQw + i];
                if (r > 0) theta += qw[((g * DPT + (r - 1)) * NQw + i) * 3 + 2];
                const float* q = qw + ((size_t)(g * DPT + r) * NQw + i) * 3;
                M = mmul(ry_m(q[1]), mmul(rx_m(q[0]), ry_m(theta)));
            } else {
                const float* m = mw + ((size_t)g * NQw + i) * 3;
                float t2 = qw[((g * DPT + 3) * NQw + i) * 3 + 2];
                M = mmul(u3_m(m[0], m[1], m[2]), ry_m(t2));
            }
            m0=M.m00.re; m1=M.m00.im; m2=M.m01.re; m3=M.m01.im;
            m4=M.m10.re; m5=M.m10.im; m6=M.m11.re; m7=M.m11.im;
        }

#pragma unroll
        for (int i = 0; i < 5; i++){
            const float c0=__shfl_sync(FULL,m0,i), c1=__shfl_sync(FULL,m1,i);
            const float c2=__shfl_sync(FULL,m2,i), c3=__shfl_sync(FULL,m3,i);
            const float c4=__shfl_sync(FULL,m4,i), c5=__shfl_sync(FULL,m5,i);
            const float c6=__shfl_sync(FULL,m6,i), c7=__shfl_sync(FULL,m7,i);
            const int lb = 4 - i, msk = 1 << lb;
            const bool hb = (l >> lb) & 1;
            const float aR = hb ? c6 : c0, aI = hb ? c7 : c1;
            const float bR = hb ? c4 : c2, bI = hb ? c5 : c3;
            const u64 PaR = dup2(aR), NaI = dup2(-aI), QaI = dup2(aI);
            const u64 PbR = dup2(bR), NbI = dup2(-bI), QbI = dup2(bI);
#pragma unroll
            for (int k = 0; k < 16; k++){
                u64 pr  = __shfl_xor_sync(FULL, vr[k], msk);
                u64 pim = __shfl_xor_sync(FULL, vi[k], msk);
                u64 orr = vr[k], oii = vi[k];
                vr[k] = f2fma(PaR, orr, f2fma(NaI, oii, f2fma(PbR, pr,  f2mul(NbI, pim))));
                vi[k] = f2fma(PaR, oii, f2fma(QaI, orr, f2fma(PbR, pim, f2mul(QbI, pr))));
            }
        }

#pragma unroll
        for (int w = 5; w <= 8; w++){
            const float c0=__shfl_sync(FULL,m0,w), c1=__shfl_sync(FULL,m1,w);
            const float c2=__shfl_sync(FULL,m2,w), c3=__shfl_sync(FULL,m3,w);
            const float c4=__shfl_sync(FULL,m4,w), c5=__shfl_sync(FULL,m5,w);
            const float c6=__shfl_sync(FULL,m6,w), c7=__shfl_sync(FULL,m7,w);
            const u64 Pr00=dup2(c0), Ni00=dup2(-c1), Qi00=dup2(c1);
            const u64 Pr01=dup2(c2), Ni01=dup2(-c3), Qi01=dup2(c3);
            const u64 Pr10=dup2(c4), Ni10=dup2(-c5), Qi10=dup2(c5);
            const u64 Pr11=dup2(c6), Ni11=dup2(-c7), Qi11=dup2(c7);
            const int SBc = 8 - w;
#pragma unroll
            for (int kk = 0; kk < 8; kk++){
                const int k0 = ((kk >> SBc) << (SBc + 1)) | (kk & ((1 << SBc) - 1));
                const int k1 = k0 | (1 << SBc);
                u64 a0r = vr[k0], a0i = vi[k0], a1r = vr[k1], a1i = vi[k1];
                vr[k0] = f2fma(Pr00, a0r, f2fma(Ni00, a0i, f2fma(Pr01, a1r, f2mul(Ni01, a1i))));
                vi[k0] = f2fma(Pr00, a0i, f2fma(Qi00, a0r, f2fma(Pr01, a1i, f2mul(Qi01, a1r))));
                vr[k1] = f2fma(Pr10, a0r, f2fma(Ni10, a0i, f2fma(Pr11, a1r, f2mul(Ni11, a1i))));
                vi[k1] = f2fma(Pr10, a0i, f2fma(Qi10, a0r, f2fma(Pr11, a1i, f2mul(Qi11, a1r))));
            }
        }

        {
            const float c0=__shfl_sync(FULL,m0,9), c1=__shfl_sync(FULL,m1,9);
            const float c2=__shfl_sync(FULL,m2,9), c3=__shfl_sync(FULL,m3,9);
            const float c4=__shfl_sync(FULL,m4,9), c5=__shfl_sync(FULL,m5,9);
            const float c6=__shfl_sync(FULL,m6,9), c7=__shfl_sync(FULL,m7,9);
            const u64 P1 = pk2(c0, c6),  P2 = pk2(c2, c4);
            const u64 N1 = pk2(-c1, -c7), N2 = pk2(-c3, -c5);
            const u64 Q1 = pk2(c1, c7),  Q2 = pk2(c3, c5);
#pragma unroll
            for (int k = 0; k < 16; k++){
                u64 xr = vr[k], xi_ = vi[k];
                u64 xsr = swp(xr), xsi = swp(xi_);
                vr[k] = f2fma(P1, xr,  f2fma(P2, xsr, f2fma(N1, xi_, f2mul(N2, xsi))));
                vi[k] = f2fma(P1, xi_, f2fma(P2, xsi, f2fma(Q1, xr,  f2mul(Q2, xsr))));
            }
        }

        if (r < 4){
            __syncwarp();
            u64 tr[16];
#pragma unroll
            for (int k = 0; k < 16; k++) *(u64*)&buf[l * 34 + 2 * k] = vr[k];
            __syncwarp();
#pragma unroll
            for (int k = 0; k < 16; k++){
                const int j0 = 2 * k;
                const int zj0 = ((j0&1)?B1:0) ^ ((j0&2)?B2:0) ^ ((j0&4)?B4:0) ^ ((j0&8)?B8:0) ^ ((j0&16)?B16:0);
                const int zj1 = zj0 ^ B1;
                const int z0 = zl ^ zj0, z1 = zl ^ zj1;
                tr[k] = pk2(buf[(z0 >> 5) * 34 + (z0 & 31)],
                            buf[(z1 >> 5) * 34 + (z1 & 31)]);
            }
            __syncwarp();
#pragma unroll
            for (int k = 0; k < 16; k++) *(u64*)&buf[l * 34 + 2 * k] = vi[k];
            __syncwarp();
#pragma unroll
            for (int k = 0; k < 16; k++){
                const int j0 = 2 * k;
                const int zj0 = ((j0&1)?B1:0) ^ ((j0&2)?B2:0) ^ ((j0&4)?B4:0) ^ ((j0&8)?B8:0) ^ ((j0&16)?B16:0);
                const int zj1 = zj0 ^ B1;
                const int z0 = zl ^ zj0, z1 = zl ^ zj1;
                vi[k] = pk2(buf[(z0 >> 5) * 34 + (z0 & 31)],
                            buf[(z1 >> 5) * 34 + (z1 & 31)]);
                vr[k] = tr[k];
            }
            __syncwarp();
        }
    }

    __syncwarp();
#pragma unroll
    for (int k = 0; k < 16; k++)
        *(u64*)&buf[l * 34 + 2 * k] = f2fma(vr[k], vr[k], f2mul(vi[k], vi[k]));
    __syncwarp();
    const size_t o = (size_t)b * GQ + (size_t)g * QD;
#pragma unroll
    for (int j = 0; j < 32; j++)
        probs[o + j * 32 + l] = rna_tf32(buf[j * 34 + l]);
}

// ---------------- launch ----------------
extern "C" void kernel_launch(void* const* d_in, const int* in_sizes, int n_in,
                              void* d_out, int out_size)
{
    const float* x          = (const float*)d_in[0];
    const float* inp_scale  = (const float*)d_in[1];
    const float* proj_in_w  = (const float*)d_in[2];
    const float* proj_in_b  = (const float*)d_in[3];
    const float* reup_w     = (const float*)d_in[4];
    const float* reup_b     = (const float*)d_in[5];
    const float* q_weights  = (const float*)d_in[6];
    const float* upload_sc  = (const float*)d_in[7];
    const float* meas_w     = (const float*)d_in[8];
    const float* proj_out_w = (const float*)d_in[9];
    const float* proj_out_b = (const float*)d_in[10];
    float* out = (float*)d_out;

    void *pxq, *pprobs, *pang, *pxs, *pwi, *pwo, *ppart;
    cudaGetSymbolAddress(&pxq,    g_xq);
    cudaGetSymbolAddress(&pprobs, g_probs);
    cudaGetSymbolAddress(&pang,   g_ang);
    cudaGetSymbolAddress(&pxs,    g_xs);
    cudaGetSymbolAddress(&pwi,    g_wi);
    cudaGetSymbolAddress(&pwo,    g_wo);
    cudaGetSymbolAddress(&ppart,  g_part);
    float* xq    = (float*)pxq;
    float* probs = (float*)pprobs;
    float* angp  = (float*)pang;
    float* xs    = (float*)pxs;
    float* wi    = (float*)pwi;
    float* wo    = (float*)pwo;
    float* part  = (float*)ppart;

    cudaFuncSetAttribute(tf32_gemm, cudaFuncAttributeMaxDynamicSharedMemorySize, 208896);

    // ---- side streams + events (R13 passing footprint: 2 streams, 4 events)
    static cudaStream_t s1 = nullptr, s2 = nullptr;
    static cudaEvent_t ev_fork = nullptr, ev_wi = nullptr, ev_wo = nullptr, ev_ang = nullptr;
    if (!ev_fork){
        if (cudaStreamCreateWithFlags(&s1, cudaStreamNonBlocking) != cudaSuccess) s1 = nullptr;
        if (cudaStreamCreateWithFlags(&s2, cudaStreamNonBlocking) != cudaSuccess) s2 = nullptr;
        cudaEventCreateWithFlags(&ev_fork, cudaEventDisableTiming);
        cudaEventCreateWithFlags(&ev_wi,   cudaEventDisableTiming);
        cudaEventCreateWithFlags(&ev_wo,   cudaEventDisableTiming);
        cudaEventCreateWithFlags(&ev_ang,  cudaEventDisableTiming);
    }
    const cudaStream_t S1 = s1 ? s1 : (cudaStream_t)0;
    const cudaStream_t S2 = s2 ? s2 : (cudaStream_t)0;

    // fork
    cudaEventRecord(ev_fork, 0);
    cudaStreamWaitEvent(S1, ev_fork, 0);
    cudaStreamWaitEvent(S2, ev_fork, 0);

    // S1: round proj_in_w -> tf32 (gates GEMM-in)
    round_tf32v<<<(GQ*INd/4 + 255)/256, 256, 0, S1>>>((const float4*)proj_in_w, nullptr,
        (float4*)wi, GQ*INd/4);
    cudaEventRecord(ev_wi, S1);

    // S2: round proj_out_w -> tf32 (gates GEMM-out), then angles (gates quantum)
    round_tf32v<<<(OUTd*GQ/4 + 255)/256, 256, 0, S2>>>((const float4*)proj_out_w, nullptr,
        (float4*)wo, OUTd*GQ/4);
    cudaEventRecord(ev_wo, S2);
    angles_kernel<<<Bsz, 320, 0, S2>>>(x, inp_scale, reup_w, reup_b, angp);
    cudaEventRecord(ev_ang, S2);

    // main chain: x * scale -> tf32
    round_tf32v<<<(Bsz*INd/4 + 255)/256, 256>>>((const float4*)x, inp_scale,
        (float4*)xs, Bsz*INd/4);

    // join wi -> GEMM-in (tf32): xq[1024,4096] = xs @ wi^T + b
    cudaStreamWaitEvent((cudaStream_t)0, ev_wi, 0);
    {
        dim3 grid(GQ/128, Bsz/256, 1);    // 32 x 4 = 128 CTAs, 1 wave
        tf32_gemm<<<grid, 256, 208896>>>(Bsz, GQ, INd, xs, wi, proj_in_b, xq);
    }

    // join angles -> quantum circuit (4096 states, one warp each)
    cudaStreamWaitEvent((cudaStream_t)0, ev_ang, 0);
    quantum_pk<<<1024, 128>>>(xq, angp, q_weights, upload_sc, meas_w, probs);

    // join wo -> GEMM-out (tf32, split-K x4): part[z] = probs @ wo^T (K slice)
    cudaStreamWaitEvent((cudaStream_t)0, ev_wo, 0);
    {
        dim3 grid(OUTd/128, Bsz/256, 4);  // 8 x 4 x 4 = 128 CTAs, 1 wave
        tf32_gemm<<<grid, 256, 208896>>>(Bsz, OUTd, GQ, probs, wo, nullptr, part);
    }
    // reduce partials + bias -> out
    reduce4<<<(Bsz*OUTd/4 + 255)/256, 256>>>((const float4*)part, proj_out_b,
        (float4*)out, Bsz*OUTd/4);
}

// round 15
// speedup vs baseline: 1.2934x; 1.0021x over previous
#include <cuda_runtime.h>
#include <cuda_bf16.h>
#include <math.h>
#include <cstdint>

#define Bsz  1024
#define INd  1024
#define OUTd 1024
#define NQw  10
#define Gg   4
#define DPT  4
#define QD   1024
#define GQ   4096   // G * QDIM

typedef unsigned long long u64;

// ---------------- scratch (device globals: no allocation allowed) ----------
__device__ float g_xq[Bsz * GQ];        // 16 MB (GEMM-in output, fp32)
__device__ float g_probs[Bsz * GQ];     // 16 MB (quantum output, tf32-rounded)
__device__ float g_ang[Bsz * Gg * NQw]; // 160 KB
__device__ float g_xs[Bsz * INd];       // 4 MB  (x*scale, tf32-rounded)
__device__ float g_part[4 * Bsz * OUTd];// 16 MB (gout split-K partials)

// ================= small PTX helpers (family-stable only; NO tcgen05) ======
__device__ __forceinline__ uint32_t smem_u32(const void* p){
    uint32_t a;
    asm("{ .reg .u64 t; cvta.to.shared.u64 t, %1; cvt.u32.u64 %0, t; }" : "=r"(a) : "l"(p));
    return a;
}
__device__ __forceinline__ void cp16(uint32_t s, const void* g){
    asm volatile("cp.async.cg.shared.global [%0], [%1], 16;" :: "r"(s), "l"(g) : "memory");
}
__device__ __forceinline__ uint32_t lds32(uint32_t a){
    uint32_t v;
    asm volatile("ld.shared.b32 %0, [%1];" : "=r"(v) : "r"(a));
    return v;
}
__device__ __forceinline__ float rna_tf32(float x){
    uint32_t t;
    asm("cvt.rna.tf32.f32 %0, %1;" : "=r"(t) : "f"(x));
    return __uint_as_float(t);
}
__device__ __forceinline__ uint32_t rna_tf32_u(uint32_t x){
    uint32_t t;
    asm("cvt.rna.tf32.f32 %0, %1;" : "=r"(t) : "f"(__uint_as_float(x)));
    return t;
}
__device__ __forceinline__ void mma_tf32(float* c, const uint32_t* a, const uint32_t* b){
    asm volatile(
        "mma.sync.aligned.m16n8k8.row.col.f32.tf32.tf32.f32 "
        "{%0,%1,%2,%3}, {%4,%5,%6,%7}, {%8,%9}, {%0,%1,%2,%3};"
        : "+f"(c[0]), "+f"(c[1]), "+f"(c[2]), "+f"(c[3])
        : "r"(a[0]), "r"(a[1]), "r"(a[2]), "r"(a[3]), "r"(b[0]), "r"(b[1]));
}

// ---- packed f32x2 (PTX ISA 8.6, sm_100+ family-generic) ----
__device__ __forceinline__ u64 f2fma(u64 a, u64 b, u64 c){
    u64 d; asm("fma.rn.f32x2 %0, %1, %2, %3;" : "=l"(d) : "l"(a), "l"(b), "l"(c)); return d;
}
__device__ __forceinline__ u64 f2mul(u64 a, u64 b){
    u64 d; asm("mul.rn.f32x2 %0, %1, %2;" : "=l"(d) : "l"(a), "l"(b)); return d;
}
__device__ __forceinline__ u64 pk2(float lo, float hi){
    u64 r;
    asm("mov.b64 %0, {%1, %2};" : "=l"(r) : "r"(__float_as_uint(lo)), "r"(__float_as_uint(hi)));
    return r;
}
__device__ __forceinline__ u64 dup2(float x){ return pk2(x, x); }
__device__ __forceinline__ void unpk(u64 v, float& a, float& b){
    uint32_t x, y;
    asm("mov.b64 {%0, %1}, %2;" : "=r"(x), "=r"(y) : "l"(v));
    a = __uint_as_float(x); b = __uint_as_float(y);
}
__device__ __forceinline__ u64 swp(u64 v){ float a, b; unpk(v, a, b); return pk2(b, a); }

// ================= tf32 rounding pass (optionally scaled), float4 ==========
__global__ void __launch_bounds__(256)
round_tf32v(const float4* __restrict__ src, const float* __restrict__ scale,
            float4* __restrict__ dst, int n4)
{
    int i = blockIdx.x * 256 + threadIdx.x;
    if (i < n4){
        float4 v = src[i];
        if (scale){
            int k = (4 * i) & (INd - 1);
            v.x *= scale[k]; v.y *= scale[k + 1]; v.z *= scale[k + 2]; v.w *= scale[k + 3];
        }
        v.x = rna_tf32(v.x); v.y = rna_tf32(v.y);
        v.z = rna_tf32(v.z); v.w = rna_tf32(v.w);
        dst[i] = v;
    }
}

// ================= split-K reduce: out = sum_z part[z] + bias ==============
__global__ void __launch_bounds__(256)
reduce4(const float4* __restrict__ part, const float* __restrict__ bias,
        float4* __restrict__ out, int n4)
{
    int i = blockIdx.x * 256 + threadIdx.x;
    if (i < n4){
        float4 a = part[i];
        float4 b = part[i + n4];
        float4 c = part[i + 2 * n4];
        float4 d = part[i + 3 * n4];
        int cb = (4 * i) & (OUTd - 1);
        float4 r;
        r.x = a.x + b.x + c.x + d.x + bias[cb];
        r.y = a.y + b.y + c.y + d.y + bias[cb + 1];
        r.z = a.z + b.z + c.z + d.z + bias[cb + 2];
        r.w = a.w + b.w + c.w + d.w + bias[cb + 3];
        out[i] = r;
    }
}

// ================= TF32 GEMM: C[M,N] = A[M,K] @ B[N,K]^T (+ bias) ==========
// A pre-rounded to tf32; B rounded INLINE at fragment load (RB=true) so the
// raw weight tensor is consumed directly (no separate rounding pass).
// CTA tile 256 x 128, BK=64, 8 warps (4m x 2n), warp tile 64 x 64.
// Split-K over blockIdx.z; bias may be null (partials).
// SMEM rows: 68 floats (272B) -> conflict-free lds32.
template<bool RB>
__global__ void __launch_bounds__(256)
tf32_gemm(int M, int N, int K,
          const float* __restrict__ A, const float* __restrict__ B,
          const float* __restrict__ bias, float* __restrict__ C)
{
    constexpr int RS   = 272;             // bytes per row (68 floats)
    constexpr int A_BY = 256 * RS;        // 69632
    constexpr int B_BY = 128 * RS;        // 34816
    constexpr int STG_ = A_BY + B_BY;     // 104448
    extern __shared__ char smc[];

    const int tid  = threadIdx.x;
    const int wid  = tid >> 5, lane = tid & 31;
    const int grp  = lane >> 2, tig = lane & 3;
    const int wm   = wid & 3,  wn = wid >> 2;       // 4 x 2 warp grid
    const int m0   = blockIdx.y * 256, n0 = blockIdx.x * 128;
    const uint32_t sb = smem_u32(smc);

    const int Kz    = K / gridDim.z;                // K per split
    const int kbase = blockIdx.z * Kz;
    C += (size_t)blockIdx.z * M * N;

    float c[4][8][4];
#pragma unroll
    for (int mt = 0; mt < 4; mt++)
#pragma unroll
        for (int nt = 0; nt < 8; nt++)
#pragma unroll
            for (int q = 0; q < 4; q++) c[mt][nt][q] = 0.f;

    const int nk = Kz >> 6;               // K chunks of 64

    auto do_prefetch = [&](int i){
        const int st = i & 1;
        const int k0 = kbase + (i << 6);
        const uint32_t ba = sb + st * STG_;
#pragma unroll
        for (int v = tid; v < 4096; v += 256){     // A: 256 rows x 16 x 16B
            int r = v >> 4, ch = v & 15;
            cp16(ba + r * RS + ch * 16, A + (size_t)(m0 + r) * K + k0 + ch * 4);
        }
#pragma unroll
        for (int v = tid; v < 2048; v += 256){     // B: 128 rows x 16 x 16B
            int r = v >> 4, ch = v & 15;
            cp16(ba + A_BY + r * RS + ch * 16, B + (size_t)(n0 + r) * K + k0 + ch * 4);
        }
        asm volatile("cp.async.commit_group;" ::: "memory");
    };

    do_prefetch(0);
    do_prefetch(1);

    for (int i = 0; i < nk; i++){
        if (i + 2 <= nk) asm volatile("cp.async.wait_group 1;" ::: "memory");
        else             asm volatile("cp.async.wait_group 0;" ::: "memory");
        __syncthreads();

        const uint32_t ba = sb + (i & 1) * STG_;
        const uint32_t bb = ba + A_BY;

#pragma unroll
        for (int kk = 0; kk < 8; kk++){
            uint32_t a[4][4];
#pragma unroll
            for (int mt = 0; mt < 4; mt++){
                const uint32_t oa = ba + (wm * 64 + mt * 16 + grp) * RS + (kk * 8 + tig) * 4;
                a[mt][0] = lds32(oa);
                a[mt][1] = lds32(oa + 8 * RS);
                a[mt][2] = lds32(oa + 16);
                a[mt][3] = lds32(oa + 8 * RS + 16);
            }
            uint32_t b[8][2];
#pragma unroll
            for (int nt = 0; nt < 8; nt++){
                const uint32_t ob = bb + (wn * 64 + nt * 8 + grp) * RS + (kk * 8 + tig) * 4;
                b[nt][0] = lds32(ob);
                b[nt][1] = lds32(ob + 16);
                if (RB){
                    b[nt][0] = rna_tf32_u(b[nt][0]);
                    b[nt][1] = rna_tf32_u(b[nt][1]);
                }
            }
#pragma unroll
            for (int mt = 0; mt < 4; mt++)
#pragma unroll
                for (int nt = 0; nt < 8; nt++)
                    mma_tf32(c[mt][nt], a[mt], b[nt]);
        }
        __syncthreads();
        if (i + 2 < nk) do_prefetch(i + 2);
    }

    // epilogue
#pragma unroll
    for (int mt = 0; mt < 4; mt++){
        const int row0 = m0 + wm * 64 + mt * 16 + grp;
#pragma unroll
        for (int nt = 0; nt < 8; nt++){
            const int col = n0 + wn * 64 + nt * 8 + 2 * tig;
            float b0 = 0.f, b1 = 0.f;
            if (bias){ b0 = bias[col]; b1 = bias[col + 1]; }
            float2 v0 = make_float2(c[mt][nt][0] + b0, c[mt][nt][1] + b1);
            float2 v1 = make_float2(c[mt][nt][2] + b0, c[mt][nt][3] + b1);
            *(float2*)&C[(size_t)row0       * N + col] = v0;
            *(float2*)&C[(size_t)(row0 + 8) * N + col] = v1;
        }
    }
}

// ---------------- angles: ang[b, j] = tanh((x*s) . reup_w[j] + reup_b[j]) * pi
__global__ void __launch_bounds__(320)
angles_kernel(const float* __restrict__ x, const float* __restrict__ inp_scale,
              const float* __restrict__ reup_w, const float* __restrict__ reup_b,
              float* __restrict__ ang)
{
    __shared__ float xs[INd];
    int b = blockIdx.x;
    for (int k = threadIdx.x; k < INd; k += blockDim.x)
        xs[k] = x[(size_t)b * INd + k] * inp_scale[k];
    __syncthreads();
    int warp = threadIdx.x >> 5, lane = threadIdx.x & 31;
#pragma unroll
    for (int q = 0; q < 4; q++){
        int j = warp * 4 + q;            // j in [0,40)
        const float* w = reup_w + (size_t)j * INd;
        float acc = 0.f;
        for (int k = lane; k < INd; k += 32) acc = fmaf(xs[k], w[k], acc);
#pragma unroll
        for (int o = 16; o; o >>= 1) acc += __shfl_xor_sync(0xffffffffu, acc, o);
        if (lane == 0)
            ang[(size_t)b * (Gg * NQw) + j] = tanhf(acc + reup_b[j]) * 3.14159265358979323846f;
    }
}

// ---------------- complex 2x2 helpers ----------------
struct C2 { float re, im; };
__device__ __forceinline__ C2 cmul(C2 a, C2 b){ return {a.re*b.re - a.im*b.im, a.re*b.im + a.im*b.re}; }
__device__ __forceinline__ C2 cadd(C2 a, C2 b){ return {a.re+b.re, a.im+b.im}; }
struct M2 { C2 m00, m01, m10, m11; };
__device__ __forceinline__ M2 mmul(M2 A, M2 B){  // A @ B
    M2 r;
    r.m00 = cadd(cmul(A.m00,B.m00), cmul(A.m01,B.m10));
    r.m01 = cadd(cmul(A.m00,B.m01), cmul(A.m01,B.m11));
    r.m10 = cadd(cmul(A.m10,B.m00), cmul(A.m11,B.m10));
    r.m11 = cadd(cmul(A.m10,B.m01), cmul(A.m11,B.m11));
    return r;
}
__device__ __forceinline__ M2 ry_m(float t){
    float c=cosf(0.5f*t), s=sinf(0.5f*t);
    return {{c,0.f},{-s,0.f},{s,0.f},{c,0.f}};
}
__device__ __forceinline__ M2 rx_m(float t){
    float c=cosf(0.5f*t), s=sinf(0.5f*t);
    return {{c,0.f},{0.f,-s},{0.f,-s},{c,0.f}};
}
__device__ __forceinline__ M2 u3_m(float t,float p,float l){
    float c=cosf(0.5f*t), s=sinf(0.5f*t);
    float cp=cosf(p), sp=sinf(p), cl=cosf(l), sl=sinf(l);
    M2 r;
    r.m00 = {c, 0.f};
    r.m01 = {-cl*s, -sl*s};
    r.m10 = {cp*s, sp*s};
    r.m11 = {(cp*cl - sp*sl)*c, (sp*cl + cp*sl)*c};
    return r;
}

// CNOT-ring permutation is XOR-linear: perm(a^b) = perm(a)^perm(b)
__device__ __forceinline__ int permL(int y){
#pragma unroll
    for (int k = 9; k >= 0; --k){
        int cb  = 9 - k;
        int tb2 = 9 - ((k + 1) % 10);
        y ^= ((y >> cb) & 1) << tb2;
    }
    return y;
}

// ================= quantum circuit: one WARP per (b,g) state ===============
__global__ void __launch_bounds__(128)
quantum_pk(const float* __restrict__ xq, const float* __restrict__ ang,
           const float* __restrict__ qw, const float* __restrict__ us,
           const float* __restrict__ mw, float* __restrict__ probs)
{
    __shared__ __align__(16) float ss[4][34 * 32];   // per-warp bounce (stride 34)
    const int wid = threadIdx.x >> 5, l = threadIdx.x & 31;
    const int s = blockIdx.x * 4 + wid;
    const int b = s >> 2, g = s & 3;
    const unsigned FULL = 0xffffffffu;
    float* buf = ss[wid];

    const int zl  = permL(l << 5);
    const int B1  = permL(1), B2 = permL(2), B4 = permL(4), B8 = permL(8), B16 = permL(16);

    const float* xrow = xq + (size_t)b * GQ + (size_t)g * QD;
#pragma unroll
    for (int j = 0; j < 32; j++) buf[j * 34 + l] = xrow[j * 32 + l];
    __syncwarp();
    u64 vr[16], vi[16];
    u64 acc2 = 0ull;
#pragma unroll
    for (int k = 0; k < 16; k++){
        vr[k] = *(const u64*)&buf[l * 34 + 2 * k];
        acc2  = f2fma(vr[k], vr[k], acc2);
        vi[k] = 0ull;
    }
    float na, nb; unpk(acc2, na, nb);
    float nrm = na + nb;
#pragma unroll
    for (int o = 16; o; o >>= 1) nrm += __shfl_xor_sync(FULL, nrm, o);
    const u64 iv = dup2(1.0f / (sqrtf(nrm) + 1e-9f));
#pragma unroll
    for (int k = 0; k < 16; k++) vr[k] = f2mul(iv, vr[k]);
    __syncwarp();

    for (int r = 0; r < 5; r++){
        float m0=0,m1=0,m2=0,m3=0,m4=0,m5=0,m6=0,m7=0;
        if (l < NQw){
            const int i = l;
            M2 M;
            if (r < 4){
                float a = ang[(size_t)b * (Gg * NQw) + g * NQw + i];
                float theta = a * us[(g * DPT + r) * NQw + i];
                if (r > 0) theta += qw[((g * DPT + (r - 1)) * NQw + i) * 3 + 2];
                const float* q = qw + ((size_t)(g * DPT + r) * NQw + i) * 3;
                M = mmul(ry_m(q[1]), mmul(rx_m(q[0]), ry_m(theta)));
            } else {
                const float* m = mw + ((size_t)g * NQw + i) * 3;
                float t2 = qw[((g * DPT + 3) * NQw + i) * 3 + 2];
                M = mmul(u3_m(m[0], m[1], m[2]), ry_m(t2));
            }
            m0=M.m00.re; m1=M.m00.im; m2=M.m01.re; m3=M.m01.im;
            m4=M.m10.re; m5=M.m10.im; m6=M.m11.re; m7=M.m11.im;
        }

#pragma unroll
        for (int i = 0; i < 5; i++){
            const float c0=__shfl_sync(FULL,m0,i), c1=__shfl_sync(FULL,m1,i);
            const float c2=__shfl_sync(FULL,m2,i), c3=__shfl_sync(FULL,m3,i);
            const float c4=__shfl_sync(FULL,m4,i), c5=__shfl_sync(FULL,m5,i);
            const float c6=__shfl_sync(FULL,m6,i), c7=__shfl_sync(FULL,m7,i);
            const int lb = 4 - i, msk = 1 << lb;
            const bool hb = (l >> lb) & 1;
            const float aR = hb ? c6 : c0, aI = hb ? c7 : c1;
            const float bR = hb ? c4 : c2, bI = hb ? c5 : c3;
            const u64 PaR = dup2(aR), NaI = dup2(-aI), QaI = dup2(aI);
            const u64 PbR = dup2(bR), NbI = dup2(-bI), QbI = dup2(bI);
#pragma unroll
            for (int k = 0; k < 16; k++){
                u64 pr  = __shfl_xor_sync(FULL, vr[k], msk);
                u64 pim = __shfl_xor_sync(FULL, vi[k], msk);
                u64 orr = vr[k], oii = vi[k];
                vr[k] = f2fma(PaR, orr, f2fma(NaI, oii, f2fma(PbR, pr,  f2mul(NbI, pim))));
                vi[k] = f2fma(PaR, oii, f2fma(QaI, orr, f2fma(PbR, pim, f2mul(QbI, pr))));
            }
        }

#pragma unroll
        for (int w = 5; w <= 8; w++){
            const float c0=__shfl_sync(FULL,m0,w), c1=__shfl_sync(FULL,m1,w);
            const float c2=__shfl_sync(FULL,m2,w), c3=__shfl_sync(FULL,m3,w);
            const float c4=__shfl_sync(FULL,m4,w), c5=__shfl_sync(FULL,m5,w);
            const float c6=__shfl_sync(FULL,m6,w), c7=__shfl_sync(FULL,m7,w);
            const u64 Pr00=dup2(c0), Ni00=dup2(-c1), Qi00=dup2(c1);
            const u64 Pr01=dup2(c2), Ni01=dup2(-c3), Qi01=dup2(c3);
            const u64 Pr10=dup2(c4), Ni10=dup2(-c5), Qi10=dup2(c5);
            const u64 Pr11=dup2(c6), Ni11=dup2(-c7), Qi11=dup2(c7);
            const int SBc = 8 - w;
#pragma unroll
            for (int kk = 0; kk < 8; kk++){
                const int k0 = ((kk >> SBc) << (SBc + 1)) | (kk & ((1 << SBc) - 1));
                const int k1 = k0 | (1 << SBc);
                u64 a0r = vr[k0], a0i = vi[k0], a1r = vr[k1], a1i = vi[k1];
                vr[k0] = f2fma(Pr00, a0r, f2fma(Ni00, a0i, f2fma(Pr01, a1r, f2mul(Ni01, a1i))));
                vi[k0] = f2fma(Pr00, a0i, f2fma(Qi00, a0r, f2fma(Pr01, a1i, f2mul(Qi01, a1r))));
                vr[k1] = f2fma(Pr10, a0r, f2fma(Ni10, a0i, f2fma(Pr11, a1r, f2mul(Ni11, a1i))));
                vi[k1] = f2fma(Pr10, a0i, f2fma(Qi10, a0r, f2fma(Pr11, a1i, f2mul(Qi11, a1r))));
            }
        }

        {
            const float c0=__shfl_sync(FULL,m0,9), c1=__shfl_sync(FULL,m1,9);
            const float c2=__shfl_sync(FULL,m2,9), c3=__shfl_sync(FULL,m3,9);
            const float c4=__shfl_sync(FULL,m4,9), c5=__shfl_sync(FULL,m5,9);
            const float c6=__shfl_sync(FULL,m6,9), c7=__shfl_sync(FULL,m7,9);
            const u64 P1 = pk2(c0, c6),  P2 = pk2(c2, c4);
            const u64 N1 = pk2(-c1, -c7), N2 = pk2(-c3, -c5);
            const u64 Q1 = pk2(c1, c7),  Q2 = pk2(c3, c5);
#pragma unroll
            for (int k = 0; k < 16; k++){
                u64 xr = vr[k], xi_ = vi[k];
                u64 xsr = swp(xr), xsi = swp(xi_);
                vr[k] = f2fma(P1, xr,  f2fma(P2, xsr, f2fma(N1, xi_, f2mul(N2, xsi))));
                vi[k] = f2fma(P1, xi_, f2fma(P2, xsi, f2fma(Q1, xr,  f2mul(Q2, xsr))));
            }
        }

        if (r < 4){
            __syncwarp();
            u64 tr[16];
#pragma unroll
            for (int k = 0; k < 16; k++) *(u64*)&buf[l * 34 + 2 * k] = vr[k];
            __syncwarp();
#pragma unroll
            for (int k = 0; k < 16; k++){
                const int j0 = 2 * k;
                const int zj0 = ((j0&1)?B1:0) ^ ((j0&2)?B2:0) ^ ((j0&4)?B4:0) ^ ((j0&8)?B8:0) ^ ((j0&16)?B16:0);
                const int zj1 = zj0 ^ B1;
                const int z0 = zl ^ zj0, z1 = zl ^ zj1;
                tr[k] = pk2(buf[(z0 >> 5) * 34 + (z0 & 31)],
                            buf[(z1 >> 5) * 34 + (z1 & 31)]);
            }
            __syncwarp();
#pragma unroll
            for (int k = 0; k < 16; k++) *(u64*)&buf[l * 34 + 2 * k] = vi[k];
            __syncwarp();
#pragma unroll
            for (int k = 0; k < 16; k++){
                const int j0 = 2 * k;
                const int zj0 = ((j0&1)?B1:0) ^ ((j0&2)?B2:0) ^ ((j0&4)?B4:0) ^ ((j0&8)?B8:0) ^ ((j0&16)?B16:0);
                const int zj1 = zj0 ^ B1;
                const int z0 = zl ^ zj0, z1 = zl ^ zj1;
                vi[k] = pk2(buf[(z0 >> 5) * 34 + (z0 & 31)],
                            buf[(z1 >> 5) * 34 + (z1 & 31)]);
                vr[k] = tr[k];
            }
            __syncwarp();
        }
    }

    __syncwarp();
#pragma unroll
    for (int k = 0; k < 16; k++)
        *(u64*)&buf[l * 34 + 2 * k] = f2fma(vr[k], vr[k], f2mul(vi[k], vi[k]));
    __syncwarp();
    const size_t o = (size_t)b * GQ + (size_t)g * QD;
#pragma unroll
    for (int j = 0; j < 32; j++)
        probs[o + j * 32 + l] = rna_tf32(buf[j * 34 + l]);
}

// ---------------- launch ----------------
extern "C" void kernel_launch(void* const* d_in, const int* in_sizes, int n_in,
                              void* d_out, int out_size)
{
    const float* x          = (const float*)d_in[0];
    const float* inp_scale  = (const float*)d_in[1];
    const float* proj_in_w  = (const float*)d_in[2];
    const float* proj_in_b  = (const float*)d_in[3];
    const float* reup_w     = (const float*)d_in[4];
    const float* reup_b     = (const float*)d_in[5];
    const float* q_weights  = (const float*)d_in[6];
    const float* upload_sc  = (const float*)d_in[7];
    const float* meas_w     = (const float*)d_in[8];
    const float* proj_out_w = (const float*)d_in[9];
    const float* proj_out_b = (const float*)d_in[10];
    float* out = (float*)d_out;

    void *pxq, *pprobs, *pang, *pxs, *ppart;
    cudaGetSymbolAddress(&pxq,    g_xq);
    cudaGetSymbolAddress(&pprobs, g_probs);
    cudaGetSymbolAddress(&pang,   g_ang);
    cudaGetSymbolAddress(&pxs,    g_xs);
    cudaGetSymbolAddress(&ppart,  g_part);
    float* xq    = (float*)pxq;
    float* probs = (float*)pprobs;
    float* angp  = (float*)pang;
    float* xs    = (float*)pxs;
    float* part  = (float*)ppart;

    cudaFuncSetAttribute(tf32_gemm<true>, cudaFuncAttributeMaxDynamicSharedMemorySize, 208896);

    // ---- one side stream + two events (smaller footprint than R14's) ----
    static cudaStream_t s2 = nullptr;
    static cudaEvent_t ev_fork = nullptr, ev_ang = nullptr;
    if (!ev_fork){
        if (cudaStreamCreateWithFlags(&s2, cudaStreamNonBlocking) != cudaSuccess) s2 = nullptr;
        cudaEventCreateWithFlags(&ev_fork, cudaEventDisableTiming);
        cudaEventCreateWithFlags(&ev_ang,  cudaEventDisableTiming);
    }
    const cudaStream_t S2 = s2 ? s2 : (cudaStream_t)0;

    // fork: angles on side stream (gates quantum; hides under GEMM-in)
    cudaEventRecord(ev_fork, 0);
    cudaStreamWaitEvent(S2, ev_fork, 0);
    angles_kernel<<<Bsz, 320, 0, S2>>>(x, inp_scale, reup_w, reup_b, angp);
    cudaEventRecord(ev_ang, S2);

    // main chain: x * scale -> tf32 (5 us)
    round_tf32v<<<(Bsz*INd/4 + 255)/256, 256>>>((const float4*)x, inp_scale,
        (float4*)xs, Bsz*INd/4);

    // GEMM-in (tf32, weights rounded inline): xq = xs @ proj_in_w^T + b
    {
        dim3 grid(GQ/128, Bsz/256, 1);    // 32 x 4 = 128 CTAs, 1 wave
        tf32_gemm<true><<<grid, 256, 208896>>>(Bsz, GQ, INd, xs, proj_in_w, proj_in_b, xq);
    }

    // join angles -> quantum circuit (4096 states, one warp each)
    cudaStreamWaitEvent((cudaStream_t)0, ev_ang, 0);
    quantum_pk<<<1024, 128>>>(xq, angp, q_weights, upload_sc, meas_w, probs);

    // GEMM-out (tf32, split-K x4, weights rounded inline): partials
    {
        dim3 grid(OUTd/128, Bsz/256, 4);  // 8 x 4 x 4 = 128 CTAs, 1 wave
        tf32_gemm<true><<<grid, 256, 208896>>>(Bsz, OUTd, GQ, probs, proj_out_w, nullptr, part);
    }
    // reduce partials + bias -> out
    reduce4<<<(Bsz*OUTd/4 + 255)/256, 256>>>((const float4*)part, proj_out_b,
        (float4*)out, Bsz*OUTd/4);
}